// round 13
// baseline (speedup 1.0000x reference)
#include <cuda_runtime.h>
#include <cuda_bf16.h>
#include <cstdint>

// ============================================================================
// Policy_Network — collapsed affine form, right-associated weight chain.
//   C34  = W3a@W4a                (1024x512,  0.54 G-MAC)
//   C234 = W2a@C34                (2048x512,  1.07 G-MAC)
//   E4   = [E1|A2|A3]@[C234;C34;W4a] + aug(W4b,b4)   (5248x512, 11 G-MAC)
//   G    = ctx'@E4                (8192x512, 21.6 G-MAC)
//   out  = G@W5 + b5              (8192x1024, 4.3 G-MAC)
// GEMM core: verified bulk-fed bf16 hi/lo split HMMA (R10/R12).
// ============================================================================

#define BATCH   8192
#define ADDROWS 5124

typedef __nv_bfloat16 bf16;

// tile image geometry (must match smem layout below)
#define A_STRIDE 80
#define B_STRIDE 272
#define ACH      20480        // A chunk bytes: 128 rows*80 (hi) + same (lo)
#define BCH      17408        // B chunk bytes: 32 rows*272 (hi) + same (lo)
#define AHALF    10240
#define BHALF    8704
#define STAGE_SZ (ACH + BCH)  // 37888
#define NSTAGE   3
#define SMEM_TOT (128 + NSTAGE * STAGE_SZ)

// ---------------- device scratch: operand images ----------------------------
__device__ __align__(16) char g_ctxA  [(size_t)64 * 161 * ACH];  // ctx' A-image
__device__ __align__(16) char g_catA  [(size_t)41 * 128 * ACH];  // [E1|A2|A3]
__device__ __align__(16) char g_W2aA  [(size_t)16 * 32  * ACH];
__device__ __align__(16) char g_W3aA  [(size_t)8  * 32  * ACH];
__device__ __align__(16) char g_stackB[(size_t)4  * 128 * BCH];  // [C234;C34;W4a]
__device__ __align__(16) char g_E4B   [(size_t)4  * 164 * BCH];
__device__ __align__(16) char g_GA    [(size_t)64 * 16  * ACH];  // G = ctx'@E4
__device__ __align__(16) char g_W5B   [(size_t)8  * 16  * BCH];

// ---------------- PTX helpers ----------------------------------------------
__device__ __forceinline__ uint32_t smem_u32(const void* p) {
    uint32_t a;
    asm("{ .reg .u64 t; cvta.to.shared.u64 t, %1; cvt.u32.u64 %0, t; }"
        : "=r"(a) : "l"(p));
    return a;
}
__device__ __forceinline__ void mbar_init(uint32_t m, uint32_t cnt) {
    asm volatile("mbarrier.init.shared.b64 [%0], %1;" :: "r"(m), "r"(cnt) : "memory");
}
__device__ __forceinline__ void mbar_expect_tx(uint32_t m, uint32_t bytes) {
    asm volatile("mbarrier.arrive.expect_tx.shared.b64 _, [%0], %1;"
                 :: "r"(m), "r"(bytes) : "memory");
}
__device__ __forceinline__ void mbar_arrive(uint32_t m) {
    asm volatile("mbarrier.arrive.shared.b64 _, [%0];" :: "r"(m) : "memory");
}
__device__ __forceinline__ void mbar_wait(uint32_t m, uint32_t parity) {
    asm volatile(
        "{\n\t.reg .pred P;\n\t"
        "W_%=:\n\t"
        "mbarrier.try_wait.parity.acquire.cta.shared::cta.b64 P, [%0], %1, 0x989680;\n\t"
        "@!P bra W_%=;\n\t"
        "}" :: "r"(m), "r"(parity) : "memory");
}
__device__ __forceinline__ void bulk_g2s(uint32_t dst, const void* src,
                                         uint32_t bytes, uint32_t mbar) {
    asm volatile(
        "cp.async.bulk.shared::cta.global.mbarrier::complete_tx::bytes [%0], [%1], %2, [%3];"
        :: "r"(dst), "l"(src), "r"(bytes), "r"(mbar) : "memory");
}
__device__ __forceinline__ void ldsm4(uint32_t* r, uint32_t a) {
    asm volatile("ldmatrix.sync.aligned.m8n8.x4.shared.b16 {%0,%1,%2,%3}, [%4];"
        : "=r"(r[0]), "=r"(r[1]), "=r"(r[2]), "=r"(r[3]) : "r"(a));
}
__device__ __forceinline__ void ldsm4t(uint32_t* r, uint32_t a) {
    asm volatile("ldmatrix.sync.aligned.m8n8.x4.trans.shared.b16 {%0,%1,%2,%3}, [%4];"
        : "=r"(r[0]), "=r"(r[1]), "=r"(r[2]), "=r"(r[3]) : "r"(a));
}
__device__ __forceinline__ void mma16816(float* d, const uint32_t* a, const uint32_t* b) {
    asm volatile(
        "mma.sync.aligned.m16n8k16.row.col.f32.bf16.bf16.f32 "
        "{%0,%1,%2,%3}, {%4,%5,%6,%7}, {%8,%9}, {%0,%1,%2,%3};"
        : "+f"(d[0]), "+f"(d[1]), "+f"(d[2]), "+f"(d[3])
        : "r"(a[0]), "r"(a[1]), "r"(a[2]), "r"(a[3]), "r"(b[0]), "r"(b[1]));
}
__device__ __forceinline__ void split2(float v, bf16& h, bf16& l) {
    h = __float2bfloat16_rn(v);
    l = __float2bfloat16_rn(v - __bfloat162float(h));
}

// image writers: (m,k) into A-image / (k,n) into B-image; k/n pair-aligned even
__device__ __forceinline__ void writeA2(char* img, int nk, int m, int k,
                                        bf16 h0, bf16 h1, bf16 l0, bf16 l1) {
    char* base = img + (size_t)(m >> 7) * ((size_t)nk * ACH)
               + (size_t)(k >> 5) * ACH + (m & 127) * A_STRIDE + (k & 31) * 2;
    *reinterpret_cast<__nv_bfloat162*>(base)         = __nv_bfloat162(h0, h1);
    *reinterpret_cast<__nv_bfloat162*>(base + AHALF) = __nv_bfloat162(l0, l1);
}
__device__ __forceinline__ void writeB2(char* img, int nkB, int k, int n,
                                        bf16 h0, bf16 h1, bf16 l0, bf16 l1) {
    char* base = img + (size_t)(n >> 7) * ((size_t)nkB * BCH)
               + (size_t)(k >> 5) * BCH + (k & 31) * B_STRIDE + (n & 127) * 2;
    *reinterpret_cast<__nv_bfloat162*>(base)         = __nv_bfloat162(h0, h1);
    *reinterpret_cast<__nv_bfloat162*>(base + BHALF) = __nv_bfloat162(l0, l1);
}

// ---------------- ctx' A-image build ----------------------------------------
__global__ void build_ctx(const float* __restrict__ state,
                          const float* __restrict__ task,
                          const float* __restrict__ action) {
    int r = blockIdx.x, t = threadIdx.x;   // 256 threads
    #pragma unroll 2
    for (int i = t; i < 1024; i += 256) {
        float4 v = reinterpret_cast<const float4*>(state + (size_t)r * 4096)[i];
        bf16 h0,l0,h1,l1,h2,l2,h3,l3;
        split2(v.x,h0,l0); split2(v.y,h1,l1); split2(v.z,h2,l2); split2(v.w,h3,l3);
        writeA2(g_ctxA, 161, r, 4*i,     h0, h1, l0, l1);
        writeA2(g_ctxA, 161, r, 4*i + 2, h2, h3, l2, l3);
    }
    if (t == 0) {
        float4 v = *reinterpret_cast<const float4*>(task + (size_t)r * 4);
        bf16 h0,l0,h1,l1,h2,l2,h3,l3;
        split2(v.x,h0,l0); split2(v.y,h1,l1); split2(v.z,h2,l2); split2(v.w,h3,l3);
        writeA2(g_ctxA, 161, r, 4096, h0, h1, l0, l1);
        writeA2(g_ctxA, 161, r, 4098, h2, h3, l2, l3);
    }
    {
        float4 v = reinterpret_cast<const float4*>(action + (size_t)r * 1024)[t];
        bf16 h0,l0,h1,l1,h2,l2,h3,l3;
        split2(v.x,h0,l0); split2(v.y,h1,l1); split2(v.z,h2,l2); split2(v.w,h3,l3);
        int k = 4100 + 4*t;
        writeA2(g_ctxA, 161, r, k,     h0, h1, l0, l1);
        writeA2(g_ctxA, 161, r, k + 2, h2, h3, l2, l3);
    }
    if (t < 14) {   // k = 5124..5151 as 14 pairs
        bf16 z = __float2bfloat16_rn(0.0f);
        bf16 one = __float2bfloat16_rn(1.0f);
        int k = 5124 + 2*t;
        writeA2(g_ctxA, 161, r, k, (t == 0) ? one : z, z, z, z);
    }
}

// ---------------- concat A-image: [E1 | A2 | A3] (5248 x 4096) --------------
// E1 = [W1;b1] cols 0..2047; A2 = [W2 rows 2048..;b2] cols 2048..3071;
// A3 = [W3 rows 1024..;b3] cols 3072..4095. Pad rows (>5124) zero.
__global__ void split_cat(const float* __restrict__ W1, const float* __restrict__ b1,
                          const float* __restrict__ W2, const float* __restrict__ b2,
                          const float* __restrict__ W3, const float* __restrict__ b3) {
    int m = blockIdx.x;          // 0..5247
    int t = threadIdx.x;         // 512 threads, 8 k each
    int k0 = t * 8;
    const float* src = nullptr;
    if (k0 < 2048) {
        if (m < ADDROWS)       src = W1 + (size_t)m * 2048 + k0;
        else if (m == ADDROWS) src = b1 + k0;
    } else if (k0 < 3072) {
        int kk = k0 - 2048;
        if (m < ADDROWS)       src = W2 + (size_t)(2048 + m) * 1024 + kk;
        else if (m == ADDROWS) src = b2 + kk;
    } else {
        int kk = k0 - 3072;
        if (m < ADDROWS)       src = W3 + (size_t)(1024 + m) * 1024 + kk;
        else if (m == ADDROWS) src = b3 + kk;
    }
    #pragma unroll
    for (int j = 0; j < 2; j++) {
        float4 v = make_float4(0.f, 0.f, 0.f, 0.f);
        if (src) v = *reinterpret_cast<const float4*>(src + j * 4);
        bf16 h0,l0,h1,l1,h2,l2,h3,l3;
        split2(v.x,h0,l0); split2(v.y,h1,l1); split2(v.z,h2,l2); split2(v.w,h3,l3);
        writeA2(g_catA, 128, m, k0 + j*4,     h0, h1, l0, l1);
        writeA2(g_catA, 128, m, k0 + j*4 + 2, h2, h3, l2, l3);
    }
}

// ---------------- generic A-image split (contiguous rows, K=1024) -----------
__global__ void split_a(const float* __restrict__ W, char* img, int nkA) {
    int m = blockIdx.x;
    int k = threadIdx.x * 4;     // 256 threads
    float4 v = *reinterpret_cast<const float4*>(W + (size_t)m * 1024 + k);
    bf16 h0,l0,h1,l1,h2,l2,h3,l3;
    split2(v.x,h0,l0); split2(v.y,h1,l1); split2(v.z,h2,l2); split2(v.w,h3,l3);
    writeA2(img, nkA, m, k,     h0, h1, l0, l1);
    writeA2(img, nkA, m, k + 2, h2, h3, l2, l3);
}

// ---------------- fused B-image splits (W4a -> stack+96ch, W5) --------------
struct SplitArgs {
    const float* W[2];
    char* img[2];
    int N[2];
    int nkB[2];
    unsigned long long end4[2];
};

__global__ void split_all(SplitArgs a) {
    unsigned long long e = (unsigned long long)blockIdx.x * 256 + threadIdx.x;
    unsigned long long start = 0;
    #pragma unroll
    for (int s = 0; s < 2; s++) {
        if (e < a.end4[s]) {
            unsigned long long base = (e - start) * 4;
            int N = a.N[s];
            int k = (int)(base / N), n = (int)(base % N);
            float4 v = *reinterpret_cast<const float4*>(a.W[s] + base);
            bf16 h0,l0,h1,l1,h2,l2,h3,l3;
            split2(v.x,h0,l0); split2(v.y,h1,l1);
            split2(v.z,h2,l2); split2(v.w,h3,l3);
            writeB2(a.img[s], a.nkB[s], k, n,     h0, h1, l0, l1);
            writeB2(a.img[s], a.nkB[s], k, n + 2, h2, h3, l2, l3);
            return;
        }
        start = a.end4[s];
    }
}

// ---------------- bulk-fed HMMA split GEMM, full/empty mbarriers ------------
__device__ __forceinline__ float addval(const float* AddW, const float* Addb,
                                        int r, int c, int N) {
    if (AddW && r < ADDROWS) return AddW[(size_t)r * N + c];
    if (Addb && r == ADDROWS) return Addb[c];
    return 0.0f;
}

__global__ __launch_bounds__(256, 2)
void gemm_bulk(const char* __restrict__ Aimg, const char* __restrict__ Bimg,
               int nk, int nkB, int N,
               const float* __restrict__ AddW, const float* __restrict__ Addb,
               const float* __restrict__ BiasN,   // per-column bias (fp32 out)
               float* __restrict__ Cf,
               char* __restrict__ outA, int KCo,
               char* __restrict__ outB, int KCb) {
    extern __shared__ char smem_raw[];
    const uint32_t sb = smem_u32(smem_raw);
    const uint32_t stages = sb + 128;
    // full[s] at sb + s*8 ; empty[s] at sb + 64 + s*8

    const int tid  = threadIdx.x;
    const int wid  = tid >> 5;
    const int lane = tid & 31;
    const int warp_m = (wid & 1) * 64;
    const int warp_n = (wid >> 1) * 32;
    const int block_row = blockIdx.y * 128;
    const int block_col = blockIdx.x * 128;

    const char* Abase = Aimg + (size_t)blockIdx.y * ((size_t)nk  * ACH);
    const char* Bbase = Bimg + (size_t)blockIdx.x * ((size_t)nkB * BCH);

    if (tid == 0) {
        #pragma unroll
        for (int s = 0; s < NSTAGE; s++) {
            mbar_init(sb + s * 8, 1);        // full: one bulk-pair tx
            mbar_init(sb + 64 + s * 8, 8);   // empty: one arrive per warp
        }
    }
    __syncthreads();

    if (tid == 0) {
        #pragma unroll
        for (int s = 0; s < NSTAGE; s++) {
            if (s < nk) {
                uint32_t mb = sb + s * 8;
                mbar_expect_tx(mb, STAGE_SZ);
                bulk_g2s(stages + s * STAGE_SZ,       Abase + (size_t)s * ACH, ACH, mb);
                bulk_g2s(stages + s * STAGE_SZ + ACH, Bbase + (size_t)s * BCH, BCH, mb);
            }
        }
    }

    float acc[64];
    #pragma unroll
    for (int i = 0; i < 64; i++) acc[i] = 0.0f;

    const int lr = lane & 15;
    const int lc = (lane >> 4) << 3;

    int stage = 0;
    uint32_t par = 0;
    for (int it = 0; it < nk; ++it) {
        mbar_wait(sb + stage * 8, par);      // full[stage]

        const uint32_t sA = stages + stage * STAGE_SZ;
        const uint32_t sB = sA + ACH;

        #pragma unroll
        for (int k2 = 0; k2 < 2; k2++) {
            uint32_t bh[8], bl[8];
            #pragma unroll
            for (int nb = 0; nb < 2; nb++) {
                uint32_t addr = sB + (k2 * 16 + lr) * B_STRIDE
                              + (warp_n + nb * 16 + lc) * 2;
                ldsm4t(&bh[nb * 4], addr);
                ldsm4t(&bl[nb * 4], addr + BHALF);
            }
            #pragma unroll
            for (int mi = 0; mi < 4; mi++) {
                uint32_t ah[4], al[4];
                uint32_t addr = sA + (warp_m + mi * 16 + lr) * A_STRIDE
                              + (k2 * 16 + lc) * 2;
                ldsm4(ah, addr);
                ldsm4(al, addr + AHALF);
                #pragma unroll
                for (int ni = 0; ni < 4; ni++) {
                    float* d = acc + (mi * 4 + ni) * 4;
                    mma16816(d, ah, &bh[ni * 2]);
                    mma16816(d, ah, &bl[ni * 2]);
                    mma16816(d, al, &bh[ni * 2]);
                }
            }
        }

        // this warp is done with the buffer
        if (lane == 0) mbar_arrive(sb + 64 + stage * 8);

        // producer: recycle this stage for chunk it+NSTAGE once all warps done
        if (tid == 0 && it + NSTAGE < nk) {
            mbar_wait(sb + 64 + stage * 8, par);   // empty[stage], same parity
            uint32_t mb = sb + stage * 8;
            mbar_expect_tx(mb, STAGE_SZ);
            bulk_g2s(stages + stage * STAGE_SZ,
                     Abase + (size_t)(it + NSTAGE) * ACH, ACH, mb);
            bulk_g2s(stages + stage * STAGE_SZ + ACH,
                     Bbase + (size_t)(it + NSTAGE) * BCH, BCH, mb);
        }

        if (++stage == NSTAGE) { stage = 0; par ^= 1; }
    }

    // ---- epilogue (no cross-warp smem dependency) ----
    #pragma unroll
    for (int mi = 0; mi < 4; mi++) {
        #pragma unroll
        for (int ni = 0; ni < 4; ni++) {
            const float* d = acc + (mi * 4 + ni) * 4;
            int r0 = block_row + warp_m + mi * 16 + (lane >> 2);
            int c0 = block_col + warp_n + ni * 8 + (lane & 3) * 2;
            if (Cf) {
                float b0 = BiasN ? BiasN[c0]     : 0.0f;
                float b1 = BiasN ? BiasN[c0 + 1] : 0.0f;
                *reinterpret_cast<float2*>(Cf + (size_t)r0 * N + c0) =
                    make_float2(d[0] + b0, d[1] + b1);
                *reinterpret_cast<float2*>(Cf + (size_t)(r0 + 8) * N + c0) =
                    make_float2(d[2] + b0, d[3] + b1);
            } else {
                float v00 = d[0] + addval(AddW, Addb, r0,     c0,     N);
                float v01 = d[1] + addval(AddW, Addb, r0,     c0 + 1, N);
                float v10 = d[2] + addval(AddW, Addb, r0 + 8, c0,     N);
                float v11 = d[3] + addval(AddW, Addb, r0 + 8, c0 + 1, N);
                bf16 h0,l0,h1,l1,h2,l2,h3,l3;
                split2(v00,h0,l0); split2(v01,h1,l1);
                split2(v10,h2,l2); split2(v11,h3,l3);
                if (outA) {
                    writeA2(outA, KCo, r0,     c0, h0, h1, l0, l1);
                    writeA2(outA, KCo, r0 + 8, c0, h2, h3, l2, l3);
                } else {
                    writeB2(outB, KCb, r0,     c0, h0, h1, l0, l1);
                    writeB2(outB, KCb, r0 + 8, c0, h2, h3, l2, l3);
                }
            }
        }
    }
}

// ---------------- host ------------------------------------------------------
template <typename T>
static T* sym_addr(const void* symbol) {
    void* p = nullptr;
    cudaGetSymbolAddress(&p, symbol);
    return reinterpret_cast<T*>(p);
}

extern "C" void kernel_launch(void* const* d_in, const int* in_sizes, int n_in,
                              void* d_out, int out_size) {
    const float* state  = (const float*)d_in[0];
    const float* action = (const float*)d_in[1];
    const float* task   = (const float*)d_in[2];
    // d_in[3..18]: dead cx branch weights
    const float* W_l1 = (const float*)d_in[19];
    const float* b_l1 = (const float*)d_in[20];
    const float* W_l2 = (const float*)d_in[21];
    const float* b_l2 = (const float*)d_in[22];
    const float* W_l3 = (const float*)d_in[23];
    const float* b_l3 = (const float*)d_in[24];
    const float* W_l4 = (const float*)d_in[25];
    const float* b_l4 = (const float*)d_in[26];
    const float* W_l5 = (const float*)d_in[27];
    const float* b_l5 = (const float*)d_in[28];
    float* out = (float*)d_out;

    cudaFuncSetAttribute(gemm_bulk,
                         cudaFuncAttributeMaxDynamicSharedMemorySize, SMEM_TOT);

    char* ctxA   = sym_addr<char>(g_ctxA);
    char* catA   = sym_addr<char>(g_catA);
    char* w2aA   = sym_addr<char>(g_W2aA);
    char* w3aA   = sym_addr<char>(g_W3aA);
    char* stackB = sym_addr<char>(g_stackB);
    char* e4B    = sym_addr<char>(g_E4B);
    char* gA     = sym_addr<char>(g_GA);
    char* w5B    = sym_addr<char>(g_W5B);

    // 0: ctx' A-image
    build_ctx<<<BATCH, 256>>>(state, task, action);
    // 1: concat A-image [E1|A2|A3]
    split_cat<<<5248, 512>>>(W_l1, b_l1, W_l2, b_l2, W_l3, b_l3);
    // 2,3: A-images of W2a, W3a
    split_a<<<2048, 256>>>(W_l2, w2aA, 32);
    split_a<<<1024, 256>>>(W_l3, w3aA, 32);
    // 4: B-images: W4a into stack chunks 96..127 (nkB=128), W5 (nkB=16)
    {
        SplitArgs sa;
        sa.W[0] = W_l4;               // rows 0..1023 = W4a (contiguous prefix)
        sa.img[0] = stackB + (size_t)96 * BCH;
        sa.N[0] = 512;  sa.nkB[0] = 128;
        sa.end4[0] = 1024ull * 512 / 4;
        sa.W[1] = W_l5;
        sa.img[1] = w5B;
        sa.N[1] = 1024; sa.nkB[1] = 16;
        sa.end4[1] = sa.end4[0] + 512ull * 1024 / 4;
        split_all<<<(unsigned)((sa.end4[1] + 255) / 256), 256>>>(sa);
    }

    // 5: C34 = W3a@W4a -> stack chunks 64..95
    gemm_bulk<<<dim3(4, 8), 256, SMEM_TOT>>>(
        w3aA, stackB + (size_t)96 * BCH, 32, 128, 512,
        nullptr, nullptr, nullptr, nullptr, nullptr, 0,
        stackB + (size_t)64 * BCH, 128);
    // 6: C234 = W2a@C34 -> stack chunks 0..63
    gemm_bulk<<<dim3(4, 16), 256, SMEM_TOT>>>(
        w2aA, stackB + (size_t)64 * BCH, 32, 128, 512,
        nullptr, nullptr, nullptr, nullptr, nullptr, 0,
        stackB, 128);
    // 7: E4 = [E1|A2|A3]@[C234;C34;W4a] + aug(W4b,b4) -> B-image (nkB=164)
    gemm_bulk<<<dim3(4, 41), 256, SMEM_TOT>>>(
        catA, stackB, 128, 128, 512,
        W_l4 + (size_t)1024 * 512, b_l4, nullptr, nullptr, nullptr, 0,
        e4B, 164);
    // 8: G = ctx'@E4 -> A-image (16 chunks)
    gemm_bulk<<<dim3(4, BATCH / 128), 256, SMEM_TOT>>>(
        ctxA, e4B, 161, 164, 512,
        nullptr, nullptr, nullptr, nullptr, gA, 16, nullptr, 0);
    // 9: out = G@W5 + b5
    gemm_bulk<<<dim3(8, BATCH / 128), 256, SMEM_TOT>>>(
        gA, w5B, 16, 16, 1024,
        nullptr, nullptr, b_l5, out, nullptr, 0, nullptr, 0);
}

// round 14
// speedup vs baseline: 1.0977x; 1.0977x over previous
#include <cuda_runtime.h>
#include <cuda_bf16.h>
#include <cstdint>

// ============================================================================
// Policy_Network — collapsed affine form, right-associated weight chain.
//   C34  = W3a@W4a                 (1024x512)
//   C234 = W2a@C34                 (2048x512)
//   E4   = [E1|A2|A3]@[C234;C34;W4a] + aug(W4b,b4)   (5248x512)
//   G    = ctx'@E4                 (8192x512)
//   out  = G@W5 + b5               (8192x1024)
// R14: 64-row-M-tile GEMM variant for the narrow-N GEMMs (E4 now 328 CTAs =
// full chip; was 164). Wide GEMMs (G, out) keep the verified 128-tile core.
// ============================================================================

#define BATCH   8192
#define ADDROWS 5124

typedef __nv_bfloat16 bf16;

// tile image geometry
#define A_STRIDE 80
#define B_STRIDE 272
#define ACH      20480        // 128-row A chunk: 128*80 hi + lo
#define ACH64    10240        // 64-row A chunk:  64*80 hi + lo
#define BCH      17408        // B chunk: 32*272 hi + lo
#define AHALF    10240
#define AHALF64  5120
#define BHALF    8704
#define STAGE_SZ   (ACH + BCH)     // 37888
#define STAGE_SZ64 (ACH64 + BCH)   // 27648
#define NSTAGE   3
#define SMEM_TOT   (128 + NSTAGE * STAGE_SZ)
#define SMEM_TOT64 (128 + NSTAGE * STAGE_SZ64)

// ---------------- device scratch: operand images ----------------------------
__device__ __align__(16) char g_ctxA  [(size_t)64 * 161 * ACH];    // ctx' (128-chunk)
__device__ __align__(16) char g_catA  [(size_t)82 * 128 * ACH64];  // [E1|A2|A3] (64-chunk)
__device__ __align__(16) char g_W2aA  [(size_t)32 * 32  * ACH64];
__device__ __align__(16) char g_W3aA  [(size_t)16 * 32  * ACH64];
__device__ __align__(16) char g_stackB[(size_t)4  * 128 * BCH];    // [C234;C34;W4a]
__device__ __align__(16) char g_E4B   [(size_t)4  * 164 * BCH];
__device__ __align__(16) char g_GA    [(size_t)64 * 16  * ACH];    // G (128-chunk)
__device__ __align__(16) char g_W5B   [(size_t)8  * 16  * BCH];

// ---------------- PTX helpers ----------------------------------------------
__device__ __forceinline__ uint32_t smem_u32(const void* p) {
    uint32_t a;
    asm("{ .reg .u64 t; cvta.to.shared.u64 t, %1; cvt.u32.u64 %0, t; }"
        : "=r"(a) : "l"(p));
    return a;
}
__device__ __forceinline__ void mbar_init(uint32_t m, uint32_t cnt) {
    asm volatile("mbarrier.init.shared.b64 [%0], %1;" :: "r"(m), "r"(cnt) : "memory");
}
__device__ __forceinline__ void mbar_expect_tx(uint32_t m, uint32_t bytes) {
    asm volatile("mbarrier.arrive.expect_tx.shared.b64 _, [%0], %1;"
                 :: "r"(m), "r"(bytes) : "memory");
}
__device__ __forceinline__ void mbar_arrive(uint32_t m) {
    asm volatile("mbarrier.arrive.shared.b64 _, [%0];" :: "r"(m) : "memory");
}
__device__ __forceinline__ void mbar_wait(uint32_t m, uint32_t parity) {
    asm volatile(
        "{\n\t.reg .pred P;\n\t"
        "W_%=:\n\t"
        "mbarrier.try_wait.parity.acquire.cta.shared::cta.b64 P, [%0], %1, 0x989680;\n\t"
        "@!P bra W_%=;\n\t"
        "}" :: "r"(m), "r"(parity) : "memory");
}
__device__ __forceinline__ void bulk_g2s(uint32_t dst, const void* src,
                                         uint32_t bytes, uint32_t mbar) {
    asm volatile(
        "cp.async.bulk.shared::cta.global.mbarrier::complete_tx::bytes [%0], [%1], %2, [%3];"
        :: "r"(dst), "l"(src), "r"(bytes), "r"(mbar) : "memory");
}
__device__ __forceinline__ void ldsm4(uint32_t* r, uint32_t a) {
    asm volatile("ldmatrix.sync.aligned.m8n8.x4.shared.b16 {%0,%1,%2,%3}, [%4];"
        : "=r"(r[0]), "=r"(r[1]), "=r"(r[2]), "=r"(r[3]) : "r"(a));
}
__device__ __forceinline__ void ldsm4t(uint32_t* r, uint32_t a) {
    asm volatile("ldmatrix.sync.aligned.m8n8.x4.trans.shared.b16 {%0,%1,%2,%3}, [%4];"
        : "=r"(r[0]), "=r"(r[1]), "=r"(r[2]), "=r"(r[3]) : "r"(a));
}
__device__ __forceinline__ void mma16816(float* d, const uint32_t* a, const uint32_t* b) {
    asm volatile(
        "mma.sync.aligned.m16n8k16.row.col.f32.bf16.bf16.f32 "
        "{%0,%1,%2,%3}, {%4,%5,%6,%7}, {%8,%9}, {%0,%1,%2,%3};"
        : "+f"(d[0]), "+f"(d[1]), "+f"(d[2]), "+f"(d[3])
        : "r"(a[0]), "r"(a[1]), "r"(a[2]), "r"(a[3]), "r"(b[0]), "r"(b[1]));
}
__device__ __forceinline__ void split2(float v, bf16& h, bf16& l) {
    h = __float2bfloat16_rn(v);
    l = __float2bfloat16_rn(v - __bfloat162float(h));
}

// image writers
__device__ __forceinline__ void writeA2(char* img, int nk, int m, int k,
                                        bf16 h0, bf16 h1, bf16 l0, bf16 l1) {
    char* base = img + (size_t)(m >> 7) * ((size_t)nk * ACH)
               + (size_t)(k >> 5) * ACH + (m & 127) * A_STRIDE + (k & 31) * 2;
    *reinterpret_cast<__nv_bfloat162*>(base)         = __nv_bfloat162(h0, h1);
    *reinterpret_cast<__nv_bfloat162*>(base + AHALF) = __nv_bfloat162(l0, l1);
}
__device__ __forceinline__ void writeA2_64(char* img, int nk, int m, int k,
                                           bf16 h0, bf16 h1, bf16 l0, bf16 l1) {
    char* base = img + (size_t)(m >> 6) * ((size_t)nk * ACH64)
               + (size_t)(k >> 5) * ACH64 + (m & 63) * A_STRIDE + (k & 31) * 2;
    *reinterpret_cast<__nv_bfloat162*>(base)           = __nv_bfloat162(h0, h1);
    *reinterpret_cast<__nv_bfloat162*>(base + AHALF64) = __nv_bfloat162(l0, l1);
}
__device__ __forceinline__ void writeB2(char* img, int nkB, int k, int n,
                                        bf16 h0, bf16 h1, bf16 l0, bf16 l1) {
    char* base = img + (size_t)(n >> 7) * ((size_t)nkB * BCH)
               + (size_t)(k >> 5) * BCH + (k & 31) * B_STRIDE + (n & 127) * 2;
    *reinterpret_cast<__nv_bfloat162*>(base)         = __nv_bfloat162(h0, h1);
    *reinterpret_cast<__nv_bfloat162*>(base + BHALF) = __nv_bfloat162(l0, l1);
}

// ---------------- ctx' A-image build (128-chunk) -----------------------------
__global__ void build_ctx(const float* __restrict__ state,
                          const float* __restrict__ task,
                          const float* __restrict__ action) {
    int r = blockIdx.x, t = threadIdx.x;   // 256 threads
    #pragma unroll 2
    for (int i = t; i < 1024; i += 256) {
        float4 v = reinterpret_cast<const float4*>(state + (size_t)r * 4096)[i];
        bf16 h0,l0,h1,l1,h2,l2,h3,l3;
        split2(v.x,h0,l0); split2(v.y,h1,l1); split2(v.z,h2,l2); split2(v.w,h3,l3);
        writeA2(g_ctxA, 161, r, 4*i,     h0, h1, l0, l1);
        writeA2(g_ctxA, 161, r, 4*i + 2, h2, h3, l2, l3);
    }
    if (t == 0) {
        float4 v = *reinterpret_cast<const float4*>(task + (size_t)r * 4);
        bf16 h0,l0,h1,l1,h2,l2,h3,l3;
        split2(v.x,h0,l0); split2(v.y,h1,l1); split2(v.z,h2,l2); split2(v.w,h3,l3);
        writeA2(g_ctxA, 161, r, 4096, h0, h1, l0, l1);
        writeA2(g_ctxA, 161, r, 4098, h2, h3, l2, l3);
    }
    {
        float4 v = reinterpret_cast<const float4*>(action + (size_t)r * 1024)[t];
        bf16 h0,l0,h1,l1,h2,l2,h3,l3;
        split2(v.x,h0,l0); split2(v.y,h1,l1); split2(v.z,h2,l2); split2(v.w,h3,l3);
        int k = 4100 + 4*t;
        writeA2(g_ctxA, 161, r, k,     h0, h1, l0, l1);
        writeA2(g_ctxA, 161, r, k + 2, h2, h3, l2, l3);
    }
    if (t < 14) {   // k = 5124..5151 as 14 pairs
        bf16 z = __float2bfloat16_rn(0.0f);
        bf16 one = __float2bfloat16_rn(1.0f);
        int k = 5124 + 2*t;
        writeA2(g_ctxA, 161, r, k, (t == 0) ? one : z, z, z, z);
    }
}

// ---------------- concat A-image [E1|A2|A3] (5248 x 4096, 64-chunk) ---------
__global__ void split_cat(const float* __restrict__ W1, const float* __restrict__ b1,
                          const float* __restrict__ W2, const float* __restrict__ b2,
                          const float* __restrict__ W3, const float* __restrict__ b3) {
    int m = blockIdx.x;          // 0..5247
    int t = threadIdx.x;         // 512 threads, 8 k each
    int k0 = t * 8;
    const float* src = nullptr;
    if (k0 < 2048) {
        if (m < ADDROWS)       src = W1 + (size_t)m * 2048 + k0;
        else if (m == ADDROWS) src = b1 + k0;
    } else if (k0 < 3072) {
        int kk = k0 - 2048;
        if (m < ADDROWS)       src = W2 + (size_t)(2048 + m) * 1024 + kk;
        else if (m == ADDROWS) src = b2 + kk;
    } else {
        int kk = k0 - 3072;
        if (m < ADDROWS)       src = W3 + (size_t)(1024 + m) * 1024 + kk;
        else if (m == ADDROWS) src = b3 + kk;
    }
    #pragma unroll
    for (int j = 0; j < 2; j++) {
        float4 v = make_float4(0.f, 0.f, 0.f, 0.f);
        if (src) v = *reinterpret_cast<const float4*>(src + j * 4);
        bf16 h0,l0,h1,l1,h2,l2,h3,l3;
        split2(v.x,h0,l0); split2(v.y,h1,l1); split2(v.z,h2,l2); split2(v.w,h3,l3);
        writeA2_64(g_catA, 128, m, k0 + j*4,     h0, h1, l0, l1);
        writeA2_64(g_catA, 128, m, k0 + j*4 + 2, h2, h3, l2, l3);
    }
}

// ---------------- generic 64-chunk A-image split (K=1024) --------------------
__global__ void split_a64(const float* __restrict__ W, char* img, int nkA) {
    int m = blockIdx.x;
    int k = threadIdx.x * 4;     // 256 threads
    float4 v = *reinterpret_cast<const float4*>(W + (size_t)m * 1024 + k);
    bf16 h0,l0,h1,l1,h2,l2,h3,l3;
    split2(v.x,h0,l0); split2(v.y,h1,l1); split2(v.z,h2,l2); split2(v.w,h3,l3);
    writeA2_64(img, nkA, m, k,     h0, h1, l0, l1);
    writeA2_64(img, nkA, m, k + 2, h2, h3, l2, l3);
}

// ---------------- fused B-image splits (W4a -> stack+96ch, W5) --------------
struct SplitArgs {
    const float* W[2];
    char* img[2];
    int N[2];
    int nkB[2];
    unsigned long long end4[2];
};

__global__ void split_all(SplitArgs a) {
    unsigned long long e = (unsigned long long)blockIdx.x * 256 + threadIdx.x;
    unsigned long long start = 0;
    #pragma unroll
    for (int s = 0; s < 2; s++) {
        if (e < a.end4[s]) {
            unsigned long long base = (e - start) * 4;
            int N = a.N[s];
            int k = (int)(base / N), n = (int)(base % N);
            float4 v = *reinterpret_cast<const float4*>(a.W[s] + base);
            bf16 h0,l0,h1,l1,h2,l2,h3,l3;
            split2(v.x,h0,l0); split2(v.y,h1,l1);
            split2(v.z,h2,l2); split2(v.w,h3,l3);
            writeB2(a.img[s], a.nkB[s], k, n,     h0, h1, l0, l1);
            writeB2(a.img[s], a.nkB[s], k, n + 2, h2, h3, l2, l3);
            return;
        }
        start = a.end4[s];
    }
}

// ---------------- common epilogue addend ------------------------------------
__device__ __forceinline__ float addval(const float* AddW, const float* Addb,
                                        int r, int c, int N) {
    if (AddW && r < ADDROWS) return AddW[(size_t)r * N + c];
    if (Addb && r == ADDROWS) return Addb[c];
    return 0.0f;
}

// ---------------- 128-tile bulk GEMM (verified core) -------------------------
__global__ __launch_bounds__(256, 2)
void gemm_bulk(const char* __restrict__ Aimg, const char* __restrict__ Bimg,
               int nk, int nkB, int N,
               const float* __restrict__ AddW, const float* __restrict__ Addb,
               const float* __restrict__ BiasN,
               float* __restrict__ Cf,
               char* __restrict__ outA, int KCo,
               char* __restrict__ outB, int KCb) {
    extern __shared__ char smem_raw[];
    const uint32_t sb = smem_u32(smem_raw);
    const uint32_t stages = sb + 128;

    const int tid  = threadIdx.x;
    const int wid  = tid >> 5;
    const int lane = tid & 31;
    const int warp_m = (wid & 1) * 64;
    const int warp_n = (wid >> 1) * 32;
    const int block_row = blockIdx.y * 128;
    const int block_col = blockIdx.x * 128;

    const char* Abase = Aimg + (size_t)blockIdx.y * ((size_t)nk  * ACH);
    const char* Bbase = Bimg + (size_t)blockIdx.x * ((size_t)nkB * BCH);

    if (tid == 0) {
        #pragma unroll
        for (int s = 0; s < NSTAGE; s++) {
            mbar_init(sb + s * 8, 1);
            mbar_init(sb + 64 + s * 8, 8);
        }
    }
    __syncthreads();

    if (tid == 0) {
        #pragma unroll
        for (int s = 0; s < NSTAGE; s++) {
            if (s < nk) {
                uint32_t mb = sb + s * 8;
                mbar_expect_tx(mb, STAGE_SZ);
                bulk_g2s(stages + s * STAGE_SZ,       Abase + (size_t)s * ACH, ACH, mb);
                bulk_g2s(stages + s * STAGE_SZ + ACH, Bbase + (size_t)s * BCH, BCH, mb);
            }
        }
    }

    float acc[64];
    #pragma unroll
    for (int i = 0; i < 64; i++) acc[i] = 0.0f;

    const int lr = lane & 15;
    const int lc = (lane >> 4) << 3;

    int stage = 0;
    uint32_t par = 0;
    for (int it = 0; it < nk; ++it) {
        mbar_wait(sb + stage * 8, par);

        const uint32_t sA = stages + stage * STAGE_SZ;
        const uint32_t sB = sA + ACH;

        #pragma unroll
        for (int k2 = 0; k2 < 2; k2++) {
            uint32_t bh[8], bl[8];
            #pragma unroll
            for (int nb = 0; nb < 2; nb++) {
                uint32_t addr = sB + (k2 * 16 + lr) * B_STRIDE
                              + (warp_n + nb * 16 + lc) * 2;
                ldsm4t(&bh[nb * 4], addr);
                ldsm4t(&bl[nb * 4], addr + BHALF);
            }
            #pragma unroll
            for (int mi = 0; mi < 4; mi++) {
                uint32_t ah[4], al[4];
                uint32_t addr = sA + (warp_m + mi * 16 + lr) * A_STRIDE
                              + (k2 * 16 + lc) * 2;
                ldsm4(ah, addr);
                ldsm4(al, addr + AHALF);
                #pragma unroll
                for (int ni = 0; ni < 4; ni++) {
                    float* d = acc + (mi * 4 + ni) * 4;
                    mma16816(d, ah, &bh[ni * 2]);
                    mma16816(d, ah, &bl[ni * 2]);
                    mma16816(d, al, &bh[ni * 2]);
                }
            }
        }

        if (lane == 0) mbar_arrive(sb + 64 + stage * 8);

        if (tid == 0 && it + NSTAGE < nk) {
            mbar_wait(sb + 64 + stage * 8, par);
            uint32_t mb = sb + stage * 8;
            mbar_expect_tx(mb, STAGE_SZ);
            bulk_g2s(stages + stage * STAGE_SZ,
                     Abase + (size_t)(it + NSTAGE) * ACH, ACH, mb);
            bulk_g2s(stages + stage * STAGE_SZ + ACH,
                     Bbase + (size_t)(it + NSTAGE) * BCH, BCH, mb);
        }

        if (++stage == NSTAGE) { stage = 0; par ^= 1; }
    }

    #pragma unroll
    for (int mi = 0; mi < 4; mi++) {
        #pragma unroll
        for (int ni = 0; ni < 4; ni++) {
            const float* d = acc + (mi * 4 + ni) * 4;
            int r0 = block_row + warp_m + mi * 16 + (lane >> 2);
            int c0 = block_col + warp_n + ni * 8 + (lane & 3) * 2;
            if (Cf) {
                float b0 = BiasN ? BiasN[c0]     : 0.0f;
                float b1 = BiasN ? BiasN[c0 + 1] : 0.0f;
                *reinterpret_cast<float2*>(Cf + (size_t)r0 * N + c0) =
                    make_float2(d[0] + b0, d[1] + b1);
                *reinterpret_cast<float2*>(Cf + (size_t)(r0 + 8) * N + c0) =
                    make_float2(d[2] + b0, d[3] + b1);
            } else {
                float v00 = d[0] + addval(AddW, Addb, r0,     c0,     N);
                float v01 = d[1] + addval(AddW, Addb, r0,     c0 + 1, N);
                float v10 = d[2] + addval(AddW, Addb, r0 + 8, c0,     N);
                float v11 = d[3] + addval(AddW, Addb, r0 + 8, c0 + 1, N);
                bf16 h0,l0,h1,l1,h2,l2,h3,l3;
                split2(v00,h0,l0); split2(v01,h1,l1);
                split2(v10,h2,l2); split2(v11,h3,l3);
                if (outA) {
                    writeA2(outA, KCo, r0,     c0, h0, h1, l0, l1);
                    writeA2(outA, KCo, r0 + 8, c0, h2, h3, l2, l3);
                } else {
                    writeB2(outB, KCb, r0,     c0, h0, h1, l0, l1);
                    writeB2(outB, KCb, r0 + 8, c0, h2, h3, l2, l3);
                }
            }
        }
    }
}

// ---------------- 64-tile bulk GEMM (narrow-grid variant) --------------------
__global__ __launch_bounds__(256, 2)
void gemm_bulk64(const char* __restrict__ Aimg, const char* __restrict__ Bimg,
                 int nk, int nkB, int N,
                 const float* __restrict__ AddW, const float* __restrict__ Addb,
                 char* __restrict__ outB, int KCb) {
    extern __shared__ char smem_raw[];
    const uint32_t sb = smem_u32(smem_raw);
    const uint32_t stages = sb + 128;

    const int tid  = threadIdx.x;
    const int wid  = tid >> 5;
    const int lane = tid & 31;
    const int warp_m = (wid & 1) * 32;
    const int warp_n = (wid >> 1) * 32;
    const int block_row = blockIdx.y * 64;
    const int block_col = blockIdx.x * 128;

    const char* Abase = Aimg + (size_t)blockIdx.y * ((size_t)nk  * ACH64);
    const char* Bbase = Bimg + (size_t)blockIdx.x * ((size_t)nkB * BCH);

    if (tid == 0) {
        #pragma unroll
        for (int s = 0; s < NSTAGE; s++) {
            mbar_init(sb + s * 8, 1);
            mbar_init(sb + 64 + s * 8, 8);
        }
    }
    __syncthreads();

    if (tid == 0) {
        #pragma unroll
        for (int s = 0; s < NSTAGE; s++) {
            if (s < nk) {
                uint32_t mb = sb + s * 8;
                mbar_expect_tx(mb, STAGE_SZ64);
                bulk_g2s(stages + s * STAGE_SZ64,         Abase + (size_t)s * ACH64, ACH64, mb);
                bulk_g2s(stages + s * STAGE_SZ64 + ACH64, Bbase + (size_t)s * BCH,   BCH,   mb);
            }
        }
    }

    float acc[32];
    #pragma unroll
    for (int i = 0; i < 32; i++) acc[i] = 0.0f;

    const int lr = lane & 15;
    const int lc = (lane >> 4) << 3;

    int stage = 0;
    uint32_t par = 0;
    for (int it = 0; it < nk; ++it) {
        mbar_wait(sb + stage * 8, par);

        const uint32_t sA = stages + stage * STAGE_SZ64;
        const uint32_t sB = sA + ACH64;

        #pragma unroll
        for (int k2 = 0; k2 < 2; k2++) {
            uint32_t bh[8], bl[8];
            #pragma unroll
            for (int nb = 0; nb < 2; nb++) {
                uint32_t addr = sB + (k2 * 16 + lr) * B_STRIDE
                              + (warp_n + nb * 16 + lc) * 2;
                ldsm4t(&bh[nb * 4], addr);
                ldsm4t(&bl[nb * 4], addr + BHALF);
            }
            #pragma unroll
            for (int mi = 0; mi < 2; mi++) {
                uint32_t ah[4], al[4];
                uint32_t addr = sA + (warp_m + mi * 16 + lr) * A_STRIDE
                              + (k2 * 16 + lc) * 2;
                ldsm4(ah, addr);
                ldsm4(al, addr + AHALF64);
                #pragma unroll
                for (int ni = 0; ni < 4; ni++) {
                    float* d = acc + (mi * 4 + ni) * 4;
                    mma16816(d, ah, &bh[ni * 2]);
                    mma16816(d, ah, &bl[ni * 2]);
                    mma16816(d, al, &bh[ni * 2]);
                }
            }
        }

        if (lane == 0) mbar_arrive(sb + 64 + stage * 8);

        if (tid == 0 && it + NSTAGE < nk) {
            mbar_wait(sb + 64 + stage * 8, par);
            uint32_t mb = sb + stage * 8;
            mbar_expect_tx(mb, STAGE_SZ64);
            bulk_g2s(stages + stage * STAGE_SZ64,
                     Abase + (size_t)(it + NSTAGE) * ACH64, ACH64, mb);
            bulk_g2s(stages + stage * STAGE_SZ64 + ACH64,
                     Bbase + (size_t)(it + NSTAGE) * BCH, BCH, mb);
        }

        if (++stage == NSTAGE) { stage = 0; par ^= 1; }
    }

    #pragma unroll
    for (int mi = 0; mi < 2; mi++) {
        #pragma unroll
        for (int ni = 0; ni < 4; ni++) {
            const float* d = acc + (mi * 4 + ni) * 4;
            int r0 = block_row + warp_m + mi * 16 + (lane >> 2);
            int c0 = block_col + warp_n + ni * 8 + (lane & 3) * 2;
            float v00 = d[0] + addval(AddW, Addb, r0,     c0,     N);
            float v01 = d[1] + addval(AddW, Addb, r0,     c0 + 1, N);
            float v10 = d[2] + addval(AddW, Addb, r0 + 8, c0,     N);
            float v11 = d[3] + addval(AddW, Addb, r0 + 8, c0 + 1, N);
            bf16 h0,l0,h1,l1,h2,l2,h3,l3;
            split2(v00,h0,l0); split2(v01,h1,l1);
            split2(v10,h2,l2); split2(v11,h3,l3);
            writeB2(outB, KCb, r0,     c0, h0, h1, l0, l1);
            writeB2(outB, KCb, r0 + 8, c0, h2, h3, l2, l3);
        }
    }
}

// ---------------- host ------------------------------------------------------
template <typename T>
static T* sym_addr(const void* symbol) {
    void* p = nullptr;
    cudaGetSymbolAddress(&p, symbol);
    return reinterpret_cast<T*>(p);
}

extern "C" void kernel_launch(void* const* d_in, const int* in_sizes, int n_in,
                              void* d_out, int out_size) {
    const float* state  = (const float*)d_in[0];
    const float* action = (const float*)d_in[1];
    const float* task   = (const float*)d_in[2];
    // d_in[3..18]: dead cx branch weights
    const float* W_l1 = (const float*)d_in[19];
    const float* b_l1 = (const float*)d_in[20];
    const float* W_l2 = (const float*)d_in[21];
    const float* b_l2 = (const float*)d_in[22];
    const float* W_l3 = (const float*)d_in[23];
    const float* b_l3 = (const float*)d_in[24];
    const float* W_l4 = (const float*)d_in[25];
    const float* b_l4 = (const float*)d_in[26];
    const float* W_l5 = (const float*)d_in[27];
    const float* b_l5 = (const float*)d_in[28];
    float* out = (float*)d_out;

    cudaFuncSetAttribute(gemm_bulk,
                         cudaFuncAttributeMaxDynamicSharedMemorySize, SMEM_TOT);
    cudaFuncSetAttribute(gemm_bulk64,
                         cudaFuncAttributeMaxDynamicSharedMemorySize, SMEM_TOT64);

    char* ctxA   = sym_addr<char>(g_ctxA);
    char* catA   = sym_addr<char>(g_catA);
    char* w2aA   = sym_addr<char>(g_W2aA);
    char* w3aA   = sym_addr<char>(g_W3aA);
    char* stackB = sym_addr<char>(g_stackB);
    char* e4B    = sym_addr<char>(g_E4B);
    char* gA     = sym_addr<char>(g_GA);
    char* w5B    = sym_addr<char>(g_W5B);

    // 0: ctx' A-image (128-chunk)
    build_ctx<<<BATCH, 256>>>(state, task, action);
    // 1: concat A-image [E1|A2|A3] (64-chunk)
    split_cat<<<5248, 512>>>(W_l1, b_l1, W_l2, b_l2, W_l3, b_l3);
    // 2,3: 64-chunk A-images of W2a, W3a
    split_a64<<<2048, 256>>>(W_l2, w2aA, 32);
    split_a64<<<1024, 256>>>(W_l3, w3aA, 32);
    // 4: B-images: W4a into stack chunks 96..127 (nkB=128), W5 (nkB=16)
    {
        SplitArgs sa;
        sa.W[0] = W_l4;               // rows 0..1023 = W4a
        sa.img[0] = stackB + (size_t)96 * BCH;
        sa.N[0] = 512;  sa.nkB[0] = 128;
        sa.end4[0] = 1024ull * 512 / 4;
        sa.W[1] = W_l5;
        sa.img[1] = w5B;
        sa.N[1] = 1024; sa.nkB[1] = 16;
        sa.end4[1] = sa.end4[0] + 512ull * 1024 / 4;
        split_all<<<(unsigned)((sa.end4[1] + 255) / 256), 256>>>(sa);
    }

    // 5: C34 = W3a@W4a -> stack chunks 64..95      (grid 64)
    gemm_bulk64<<<dim3(4, 16), 256, SMEM_TOT64>>>(
        w3aA, stackB + (size_t)96 * BCH, 32, 128, 512,
        nullptr, nullptr, stackB + (size_t)64 * BCH, 128);
    // 6: C234 = W2a@C34 -> stack chunks 0..63      (grid 128)
    gemm_bulk64<<<dim3(4, 32), 256, SMEM_TOT64>>>(
        w2aA, stackB + (size_t)64 * BCH, 32, 128, 512,
        nullptr, nullptr, stackB, 128);
    // 7: E4 = [E1|A2|A3]@[C234;C34;W4a] + aug(W4b,b4) -> B-image (grid 328)
    gemm_bulk64<<<dim3(4, 82), 256, SMEM_TOT64>>>(
        catA, stackB, 128, 128, 512,
        W_l4 + (size_t)1024 * 512, b_l4, e4B, 164);
    // 8: G = ctx'@E4 -> A-image (128-chunk, 16 chunks)
    gemm_bulk<<<dim3(4, BATCH / 128), 256, SMEM_TOT>>>(
        ctxA, e4B, 161, 164, 512,
        nullptr, nullptr, nullptr, nullptr, gA, 16, nullptr, 0);
    // 9: out = G@W5 + b5
    gemm_bulk<<<dim3(8, BATCH / 128), 256, SMEM_TOT>>>(
        gA, w5B, 16, 16, 1024,
        nullptr, nullptr, b_l5, out, nullptr, 0, nullptr, 0);
}

// round 15
// speedup vs baseline: 1.3441x; 1.2245x over previous
#include <cuda_runtime.h>
#include <cuda_bf16.h>
#include <cuda_fp16.h>
#include <cstdint>

// ============================================================================
// Policy_Network — collapsed affine, right-associated chain, mixed precision.
//   C34  = W3a@W4a ; C234 = W2a@C34          (bf16 3-MMA, 64-tile)
//   E4   = [E1|A2|A3]@[C234;C34;W4a] + aug   (bf16 3-MMA, 64-tile, fp16 out)
//   G    = ctx'@E4                           (fp16 2-MMA: A plain fp16, B split)
//   out  = G@W5 + b5                         (bf16 3-MMA, 128-tile)
// fp16-2MMA error ~2^-12*1.5 ≈ 3.7e-4 < 1e-3 threshold.
// ============================================================================

#define BATCH   8192
#define ADDROWS 5124

typedef __nv_bfloat16 bf16;

// tile image geometry
#define A_STRIDE 80
#define B_STRIDE 272
#define ACH      20480        // 128-row split A chunk (hi+lo)
#define ACH64    10240        // 64-row split A chunk
#define ACHH     10240        // 128-row single fp16 A chunk
#define BCH      17408        // B chunk (hi+lo)
#define AHALF    10240
#define AHALF64  5120
#define BHALF    8704
#define STAGE_SZ   (ACH + BCH)     // 37888
#define STAGE_SZ64 (ACH64 + BCH)   // 27648
#define STAGE_SZH  (ACHH + BCH)    // 27648
#define NSTAGE   3
#define SMEM_TOT   (128 + NSTAGE * STAGE_SZ)
#define SMEM_TOT64 (128 + NSTAGE * STAGE_SZ64)
#define SMEM_TOTH  (128 + NSTAGE * STAGE_SZH)

// ---------------- device scratch: operand images ----------------------------
__device__ __align__(16) char g_ctxH  [(size_t)64 * 161 * ACHH];   // ctx' fp16
__device__ __align__(16) char g_catA  [(size_t)82 * 128 * ACH64];  // [E1|A2|A3]
__device__ __align__(16) char g_W2aA  [(size_t)32 * 32  * ACH64];
__device__ __align__(16) char g_W3aA  [(size_t)16 * 32  * ACH64];
__device__ __align__(16) char g_stackB[(size_t)4  * 128 * BCH];    // [C234;C34;W4a]
__device__ __align__(16) char g_E4B   [(size_t)4  * 164 * BCH];    // fp16 hi/lo
__device__ __align__(16) char g_GA    [(size_t)64 * 16  * ACH];    // G bf16 split
__device__ __align__(16) char g_W5B   [(size_t)8  * 16  * BCH];

// ---------------- PTX helpers ----------------------------------------------
__device__ __forceinline__ uint32_t smem_u32(const void* p) {
    uint32_t a;
    asm("{ .reg .u64 t; cvta.to.shared.u64 t, %1; cvt.u32.u64 %0, t; }"
        : "=r"(a) : "l"(p));
    return a;
}
__device__ __forceinline__ void mbar_init(uint32_t m, uint32_t cnt) {
    asm volatile("mbarrier.init.shared.b64 [%0], %1;" :: "r"(m), "r"(cnt) : "memory");
}
__device__ __forceinline__ void mbar_expect_tx(uint32_t m, uint32_t bytes) {
    asm volatile("mbarrier.arrive.expect_tx.shared.b64 _, [%0], %1;"
                 :: "r"(m), "r"(bytes) : "memory");
}
__device__ __forceinline__ void mbar_arrive(uint32_t m) {
    asm volatile("mbarrier.arrive.shared.b64 _, [%0];" :: "r"(m) : "memory");
}
__device__ __forceinline__ void mbar_wait(uint32_t m, uint32_t parity) {
    asm volatile(
        "{\n\t.reg .pred P;\n\t"
        "W_%=:\n\t"
        "mbarrier.try_wait.parity.acquire.cta.shared::cta.b64 P, [%0], %1, 0x989680;\n\t"
        "@!P bra W_%=;\n\t"
        "}" :: "r"(m), "r"(parity) : "memory");
}
__device__ __forceinline__ void bulk_g2s(uint32_t dst, const void* src,
                                         uint32_t bytes, uint32_t mbar) {
    asm volatile(
        "cp.async.bulk.shared::cta.global.mbarrier::complete_tx::bytes [%0], [%1], %2, [%3];"
        :: "r"(dst), "l"(src), "r"(bytes), "r"(mbar) : "memory");
}
__device__ __forceinline__ void ldsm4(uint32_t* r, uint32_t a) {
    asm volatile("ldmatrix.sync.aligned.m8n8.x4.shared.b16 {%0,%1,%2,%3}, [%4];"
        : "=r"(r[0]), "=r"(r[1]), "=r"(r[2]), "=r"(r[3]) : "r"(a));
}
__device__ __forceinline__ void ldsm4t(uint32_t* r, uint32_t a) {
    asm volatile("ldmatrix.sync.aligned.m8n8.x4.trans.shared.b16 {%0,%1,%2,%3}, [%4];"
        : "=r"(r[0]), "=r"(r[1]), "=r"(r[2]), "=r"(r[3]) : "r"(a));
}
__device__ __forceinline__ void mma16816(float* d, const uint32_t* a, const uint32_t* b) {
    asm volatile(
        "mma.sync.aligned.m16n8k16.row.col.f32.bf16.bf16.f32 "
        "{%0,%1,%2,%3}, {%4,%5,%6,%7}, {%8,%9}, {%0,%1,%2,%3};"
        : "+f"(d[0]), "+f"(d[1]), "+f"(d[2]), "+f"(d[3])
        : "r"(a[0]), "r"(a[1]), "r"(a[2]), "r"(a[3]), "r"(b[0]), "r"(b[1]));
}
__device__ __forceinline__ void mma16816h(float* d, const uint32_t* a, const uint32_t* b) {
    asm volatile(
        "mma.sync.aligned.m16n8k16.row.col.f32.f16.f16.f32 "
        "{%0,%1,%2,%3}, {%4,%5,%6,%7}, {%8,%9}, {%0,%1,%2,%3};"
        : "+f"(d[0]), "+f"(d[1]), "+f"(d[2]), "+f"(d[3])
        : "r"(a[0]), "r"(a[1]), "r"(a[2]), "r"(a[3]), "r"(b[0]), "r"(b[1]));
}
__device__ __forceinline__ void split2(float v, bf16& h, bf16& l) {
    h = __float2bfloat16_rn(v);
    l = __float2bfloat16_rn(v - __bfloat162float(h));
}
__device__ __forceinline__ void split2h(float v, __half& h, __half& l) {
    h = __float2half_rn(v);
    l = __float2half_rn(v - __half2float(h));
}

// image writers
__device__ __forceinline__ void writeA2(char* img, int nk, int m, int k,
                                        bf16 h0, bf16 h1, bf16 l0, bf16 l1) {
    char* base = img + (size_t)(m >> 7) * ((size_t)nk * ACH)
               + (size_t)(k >> 5) * ACH + (m & 127) * A_STRIDE + (k & 31) * 2;
    *reinterpret_cast<__nv_bfloat162*>(base)         = __nv_bfloat162(h0, h1);
    *reinterpret_cast<__nv_bfloat162*>(base + AHALF) = __nv_bfloat162(l0, l1);
}
__device__ __forceinline__ void writeA2_64(char* img, int nk, int m, int k,
                                           bf16 h0, bf16 h1, bf16 l0, bf16 l1) {
    char* base = img + (size_t)(m >> 6) * ((size_t)nk * ACH64)
               + (size_t)(k >> 5) * ACH64 + (m & 63) * A_STRIDE + (k & 31) * 2;
    *reinterpret_cast<__nv_bfloat162*>(base)           = __nv_bfloat162(h0, h1);
    *reinterpret_cast<__nv_bfloat162*>(base + AHALF64) = __nv_bfloat162(l0, l1);
}
__device__ __forceinline__ void writeAh(char* img, int nk, int m, int k,
                                        __half h0, __half h1) {
    char* base = img + (size_t)(m >> 7) * ((size_t)nk * ACHH)
               + (size_t)(k >> 5) * ACHH + (m & 127) * A_STRIDE + (k & 31) * 2;
    *reinterpret_cast<__half2*>(base) = __half2(h0, h1);
}
__device__ __forceinline__ void writeB2(char* img, int nkB, int k, int n,
                                        bf16 h0, bf16 h1, bf16 l0, bf16 l1) {
    char* base = img + (size_t)(n >> 7) * ((size_t)nkB * BCH)
               + (size_t)(k >> 5) * BCH + (k & 31) * B_STRIDE + (n & 127) * 2;
    *reinterpret_cast<__nv_bfloat162*>(base)         = __nv_bfloat162(h0, h1);
    *reinterpret_cast<__nv_bfloat162*>(base + BHALF) = __nv_bfloat162(l0, l1);
}
__device__ __forceinline__ void writeB2h(char* img, int nkB, int k, int n,
                                         __half h0, __half h1, __half l0, __half l1) {
    char* base = img + (size_t)(n >> 7) * ((size_t)nkB * BCH)
               + (size_t)(k >> 5) * BCH + (k & 31) * B_STRIDE + (n & 127) * 2;
    *reinterpret_cast<__half2*>(base)         = __half2(h0, h1);
    *reinterpret_cast<__half2*>(base + BHALF) = __half2(l0, l1);
}

// ---------------- ctx' fp16 A-image build ------------------------------------
__global__ void build_ctx(const float* __restrict__ state,
                          const float* __restrict__ task,
                          const float* __restrict__ action) {
    int r = blockIdx.x, t = threadIdx.x;   // 256 threads
    #pragma unroll 2
    for (int i = t; i < 1024; i += 256) {
        float4 v = reinterpret_cast<const float4*>(state + (size_t)r * 4096)[i];
        writeAh(g_ctxH, 161, r, 4*i,     __float2half_rn(v.x), __float2half_rn(v.y));
        writeAh(g_ctxH, 161, r, 4*i + 2, __float2half_rn(v.z), __float2half_rn(v.w));
    }
    if (t == 0) {
        float4 v = *reinterpret_cast<const float4*>(task + (size_t)r * 4);
        writeAh(g_ctxH, 161, r, 4096, __float2half_rn(v.x), __float2half_rn(v.y));
        writeAh(g_ctxH, 161, r, 4098, __float2half_rn(v.z), __float2half_rn(v.w));
    }
    {
        float4 v = reinterpret_cast<const float4*>(action + (size_t)r * 1024)[t];
        int k = 4100 + 4*t;
        writeAh(g_ctxH, 161, r, k,     __float2half_rn(v.x), __float2half_rn(v.y));
        writeAh(g_ctxH, 161, r, k + 2, __float2half_rn(v.z), __float2half_rn(v.w));
    }
    if (t < 14) {   // k = 5124..5151 as 14 pairs
        __half z = __float2half_rn(0.0f);
        __half one = __float2half_rn(1.0f);
        int k = 5124 + 2*t;
        writeAh(g_ctxH, 161, r, k, (t == 0) ? one : z, z);
    }
}

// ---------------- concat A-image [E1|A2|A3] (5248 x 4096, 64-chunk) ---------
__global__ void split_cat(const float* __restrict__ W1, const float* __restrict__ b1,
                          const float* __restrict__ W2, const float* __restrict__ b2,
                          const float* __restrict__ W3, const float* __restrict__ b3) {
    int m = blockIdx.x;          // 0..5247
    int t = threadIdx.x;         // 512 threads, 8 k each
    int k0 = t * 8;
    const float* src = nullptr;
    if (k0 < 2048) {
        if (m < ADDROWS)       src = W1 + (size_t)m * 2048 + k0;
        else if (m == ADDROWS) src = b1 + k0;
    } else if (k0 < 3072) {
        int kk = k0 - 2048;
        if (m < ADDROWS)       src = W2 + (size_t)(2048 + m) * 1024 + kk;
        else if (m == ADDROWS) src = b2 + kk;
    } else {
        int kk = k0 - 3072;
        if (m < ADDROWS)       src = W3 + (size_t)(1024 + m) * 1024 + kk;
        else if (m == ADDROWS) src = b3 + kk;
    }
    #pragma unroll
    for (int j = 0; j < 2; j++) {
        float4 v = make_float4(0.f, 0.f, 0.f, 0.f);
        if (src) v = *reinterpret_cast<const float4*>(src + j * 4);
        bf16 h0,l0,h1,l1,h2,l2,h3,l3;
        split2(v.x,h0,l0); split2(v.y,h1,l1); split2(v.z,h2,l2); split2(v.w,h3,l3);
        writeA2_64(g_catA, 128, m, k0 + j*4,     h0, h1, l0, l1);
        writeA2_64(g_catA, 128, m, k0 + j*4 + 2, h2, h3, l2, l3);
    }
}

// ---------------- generic 64-chunk A-image split (K=1024) --------------------
__global__ void split_a64(const float* __restrict__ W, char* img, int nkA) {
    int m = blockIdx.x;
    int k = threadIdx.x * 4;     // 256 threads
    float4 v = *reinterpret_cast<const float4*>(W + (size_t)m * 1024 + k);
    bf16 h0,l0,h1,l1,h2,l2,h3,l3;
    split2(v.x,h0,l0); split2(v.y,h1,l1); split2(v.z,h2,l2); split2(v.w,h3,l3);
    writeA2_64(img, nkA, m, k,     h0, h1, l0, l1);
    writeA2_64(img, nkA, m, k + 2, h2, h3, l2, l3);
}

// ---------------- fused B-image splits (W4a -> stack+96ch, W5) --------------
struct SplitArgs {
    const float* W[2];
    char* img[2];
    int N[2];
    int nkB[2];
    unsigned long long end4[2];
};

__global__ void split_all(SplitArgs a) {
    unsigned long long e = (unsigned long long)blockIdx.x * 256 + threadIdx.x;
    unsigned long long start = 0;
    #pragma unroll
    for (int s = 0; s < 2; s++) {
        if (e < a.end4[s]) {
            unsigned long long base = (e - start) * 4;
            int N = a.N[s];
            int k = (int)(base / N), n = (int)(base % N);
            float4 v = *reinterpret_cast<const float4*>(a.W[s] + base);
            bf16 h0,l0,h1,l1,h2,l2,h3,l3;
            split2(v.x,h0,l0); split2(v.y,h1,l1);
            split2(v.z,h2,l2); split2(v.w,h3,l3);
            writeB2(a.img[s], a.nkB[s], k, n,     h0, h1, l0, l1);
            writeB2(a.img[s], a.nkB[s], k, n + 2, h2, h3, l2, l3);
            return;
        }
        start = a.end4[s];
    }
}

// ---------------- common epilogue addend ------------------------------------
__device__ __forceinline__ float addval(const float* AddW, const float* Addb,
                                        int r, int c, int N) {
    if (AddW && r < ADDROWS) return AddW[(size_t)r * N + c];
    if (Addb && r == ADDROWS) return Addb[c];
    return 0.0f;
}

// ---------------- 128-tile bulk GEMM (verified bf16 core) --------------------
__global__ __launch_bounds__(256, 2)
void gemm_bulk(const char* __restrict__ Aimg, const char* __restrict__ Bimg,
               int nk, int nkB, int N,
               const float* __restrict__ BiasN,
               float* __restrict__ Cf,
               char* __restrict__ outA, int KCo) {
    extern __shared__ char smem_raw[];
    const uint32_t sb = smem_u32(smem_raw);
    const uint32_t stages = sb + 128;

    const int tid  = threadIdx.x;
    const int wid  = tid >> 5;
    const int lane = tid & 31;
    const int warp_m = (wid & 1) * 64;
    const int warp_n = (wid >> 1) * 32;
    const int block_row = blockIdx.y * 128;
    const int block_col = blockIdx.x * 128;

    const char* Abase = Aimg + (size_t)blockIdx.y * ((size_t)nk  * ACH);
    const char* Bbase = Bimg + (size_t)blockIdx.x * ((size_t)nkB * BCH);

    if (tid == 0) {
        #pragma unroll
        for (int s = 0; s < NSTAGE; s++) {
            mbar_init(sb + s * 8, 1);
            mbar_init(sb + 64 + s * 8, 8);
        }
    }
    __syncthreads();

    if (tid == 0) {
        #pragma unroll
        for (int s = 0; s < NSTAGE; s++) {
            if (s < nk) {
                uint32_t mb = sb + s * 8;
                mbar_expect_tx(mb, STAGE_SZ);
                bulk_g2s(stages + s * STAGE_SZ,       Abase + (size_t)s * ACH, ACH, mb);
                bulk_g2s(stages + s * STAGE_SZ + ACH, Bbase + (size_t)s * BCH, BCH, mb);
            }
        }
    }

    float acc[64];
    #pragma unroll
    for (int i = 0; i < 64; i++) acc[i] = 0.0f;

    const int lr = lane & 15;
    const int lc = (lane >> 4) << 3;

    int stage = 0;
    uint32_t par = 0;
    for (int it = 0; it < nk; ++it) {
        mbar_wait(sb + stage * 8, par);

        const uint32_t sA = stages + stage * STAGE_SZ;
        const uint32_t sB = sA + ACH;

        #pragma unroll
        for (int k2 = 0; k2 < 2; k2++) {
            uint32_t bh[8], bl[8];
            #pragma unroll
            for (int nb = 0; nb < 2; nb++) {
                uint32_t addr = sB + (k2 * 16 + lr) * B_STRIDE
                              + (warp_n + nb * 16 + lc) * 2;
                ldsm4t(&bh[nb * 4], addr);
                ldsm4t(&bl[nb * 4], addr + BHALF);
            }
            #pragma unroll
            for (int mi = 0; mi < 4; mi++) {
                uint32_t ah[4], al[4];
                uint32_t addr = sA + (warp_m + mi * 16 + lr) * A_STRIDE
                              + (k2 * 16 + lc) * 2;
                ldsm4(ah, addr);
                ldsm4(al, addr + AHALF);
                #pragma unroll
                for (int ni = 0; ni < 4; ni++) {
                    float* d = acc + (mi * 4 + ni) * 4;
                    mma16816(d, ah, &bh[ni * 2]);
                    mma16816(d, ah, &bl[ni * 2]);
                    mma16816(d, al, &bh[ni * 2]);
                }
            }
        }

        if (lane == 0) mbar_arrive(sb + 64 + stage * 8);

        if (tid == 0 && it + NSTAGE < nk) {
            mbar_wait(sb + 64 + stage * 8, par);
            uint32_t mb = sb + stage * 8;
            mbar_expect_tx(mb, STAGE_SZ);
            bulk_g2s(stages + stage * STAGE_SZ,
                     Abase + (size_t)(it + NSTAGE) * ACH, ACH, mb);
            bulk_g2s(stages + stage * STAGE_SZ + ACH,
                     Bbase + (size_t)(it + NSTAGE) * BCH, BCH, mb);
        }

        if (++stage == NSTAGE) { stage = 0; par ^= 1; }
    }

    #pragma unroll
    for (int mi = 0; mi < 4; mi++) {
        #pragma unroll
        for (int ni = 0; ni < 4; ni++) {
            const float* d = acc + (mi * 4 + ni) * 4;
            int r0 = block_row + warp_m + mi * 16 + (lane >> 2);
            int c0 = block_col + warp_n + ni * 8 + (lane & 3) * 2;
            if (Cf) {
                float b0 = BiasN ? BiasN[c0]     : 0.0f;
                float b1 = BiasN ? BiasN[c0 + 1] : 0.0f;
                *reinterpret_cast<float2*>(Cf + (size_t)r0 * N + c0) =
                    make_float2(d[0] + b0, d[1] + b1);
                *reinterpret_cast<float2*>(Cf + (size_t)(r0 + 8) * N + c0) =
                    make_float2(d[2] + b0, d[3] + b1);
            } else {
                bf16 h0,l0,h1,l1,h2,l2,h3,l3;
                split2(d[0],h0,l0); split2(d[1],h1,l1);
                split2(d[2],h2,l2); split2(d[3],h3,l3);
                writeA2(outA, KCo, r0,     c0, h0, h1, l0, l1);
                writeA2(outA, KCo, r0 + 8, c0, h2, h3, l2, l3);
            }
        }
    }
}

// ---------------- 64-tile bulk GEMM (bf16 3-MMA; fp16 or bf16 split out) ----
__global__ __launch_bounds__(256, 2)
void gemm_bulk64(const char* __restrict__ Aimg, const char* __restrict__ Bimg,
                 int nk, int nkB, int N,
                 const float* __restrict__ AddW, const float* __restrict__ Addb,
                 char* __restrict__ outB, int KCb, int f16out) {
    extern __shared__ char smem_raw[];
    const uint32_t sb = smem_u32(smem_raw);
    const uint32_t stages = sb + 128;

    const int tid  = threadIdx.x;
    const int wid  = tid >> 5;
    const int lane = tid & 31;
    const int warp_m = (wid & 1) * 32;
    const int warp_n = (wid >> 1) * 32;
    const int block_row = blockIdx.y * 64;
    const int block_col = blockIdx.x * 128;

    const char* Abase = Aimg + (size_t)blockIdx.y * ((size_t)nk  * ACH64);
    const char* Bbase = Bimg + (size_t)blockIdx.x * ((size_t)nkB * BCH);

    if (tid == 0) {
        #pragma unroll
        for (int s = 0; s < NSTAGE; s++) {
            mbar_init(sb + s * 8, 1);
            mbar_init(sb + 64 + s * 8, 8);
        }
    }
    __syncthreads();

    if (tid == 0) {
        #pragma unroll
        for (int s = 0; s < NSTAGE; s++) {
            if (s < nk) {
                uint32_t mb = sb + s * 8;
                mbar_expect_tx(mb, STAGE_SZ64);
                bulk_g2s(stages + s * STAGE_SZ64,         Abase + (size_t)s * ACH64, ACH64, mb);
                bulk_g2s(stages + s * STAGE_SZ64 + ACH64, Bbase + (size_t)s * BCH,   BCH,   mb);
            }
        }
    }

    float acc[32];
    #pragma unroll
    for (int i = 0; i < 32; i++) acc[i] = 0.0f;

    const int lr = lane & 15;
    const int lc = (lane >> 4) << 3;

    int stage = 0;
    uint32_t par = 0;
    for (int it = 0; it < nk; ++it) {
        mbar_wait(sb + stage * 8, par);

        const uint32_t sA = stages + stage * STAGE_SZ64;
        const uint32_t sB = sA + ACH64;

        #pragma unroll
        for (int k2 = 0; k2 < 2; k2++) {
            uint32_t bh[8], bl[8];
            #pragma unroll
            for (int nb = 0; nb < 2; nb++) {
                uint32_t addr = sB + (k2 * 16 + lr) * B_STRIDE
                              + (warp_n + nb * 16 + lc) * 2;
                ldsm4t(&bh[nb * 4], addr);
                ldsm4t(&bl[nb * 4], addr + BHALF);
            }
            #pragma unroll
            for (int mi = 0; mi < 2; mi++) {
                uint32_t ah[4], al[4];
                uint32_t addr = sA + (warp_m + mi * 16 + lr) * A_STRIDE
                              + (k2 * 16 + lc) * 2;
                ldsm4(ah, addr);
                ldsm4(al, addr + AHALF64);
                #pragma unroll
                for (int ni = 0; ni < 4; ni++) {
                    float* d = acc + (mi * 4 + ni) * 4;
                    mma16816(d, ah, &bh[ni * 2]);
                    mma16816(d, ah, &bl[ni * 2]);
                    mma16816(d, al, &bh[ni * 2]);
                }
            }
        }

        if (lane == 0) mbar_arrive(sb + 64 + stage * 8);

        if (tid == 0 && it + NSTAGE < nk) {
            mbar_wait(sb + 64 + stage * 8, par);
            uint32_t mb = sb + stage * 8;
            mbar_expect_tx(mb, STAGE_SZ64);
            bulk_g2s(stages + stage * STAGE_SZ64,
                     Abase + (size_t)(it + NSTAGE) * ACH64, ACH64, mb);
            bulk_g2s(stages + stage * STAGE_SZ64 + ACH64,
                     Bbase + (size_t)(it + NSTAGE) * BCH, BCH, mb);
        }

        if (++stage == NSTAGE) { stage = 0; par ^= 1; }
    }

    #pragma unroll
    for (int mi = 0; mi < 2; mi++) {
        #pragma unroll
        for (int ni = 0; ni < 4; ni++) {
            const float* d = acc + (mi * 4 + ni) * 4;
            int r0 = block_row + warp_m + mi * 16 + (lane >> 2);
            int c0 = block_col + warp_n + ni * 8 + (lane & 3) * 2;
            float v00 = d[0] + addval(AddW, Addb, r0,     c0,     N);
            float v01 = d[1] + addval(AddW, Addb, r0,     c0 + 1, N);
            float v10 = d[2] + addval(AddW, Addb, r0 + 8, c0,     N);
            float v11 = d[3] + addval(AddW, Addb, r0 + 8, c0 + 1, N);
            if (f16out) {
                __half h0,l0,h1,l1,h2,l2,h3,l3;
                split2h(v00,h0,l0); split2h(v01,h1,l1);
                split2h(v10,h2,l2); split2h(v11,h3,l3);
                writeB2h(outB, KCb, r0,     c0, h0, h1, l0, l1);
                writeB2h(outB, KCb, r0 + 8, c0, h2, h3, l2, l3);
            } else {
                bf16 h0,l0,h1,l1,h2,l2,h3,l3;
                split2(v00,h0,l0); split2(v01,h1,l1);
                split2(v10,h2,l2); split2(v11,h3,l3);
                writeB2(outB, KCb, r0,     c0, h0, h1, l0, l1);
                writeB2(outB, KCb, r0 + 8, c0, h2, h3, l2, l3);
            }
        }
    }
}

// ---------------- G kernel: fp16 2-MMA, A single fp16, B fp16 hi/lo ---------
__global__ __launch_bounds__(256, 2)
void gemm_g_f16(const char* __restrict__ Aimg, const char* __restrict__ Bimg,
                int nk, int nkB, int N,
                char* __restrict__ outA, int KCo) {
    extern __shared__ char smem_raw[];
    const uint32_t sb = smem_u32(smem_raw);
    const uint32_t stages = sb + 128;

    const int tid  = threadIdx.x;
    const int wid  = tid >> 5;
    const int lane = tid & 31;
    const int warp_m = (wid & 1) * 64;
    const int warp_n = (wid >> 1) * 32;
    const int block_row = blockIdx.y * 128;
    const int block_col = blockIdx.x * 128;

    const char* Abase = Aimg + (size_t)blockIdx.y * ((size_t)nk  * ACHH);
    const char* Bbase = Bimg + (size_t)blockIdx.x * ((size_t)nkB * BCH);

    if (tid == 0) {
        #pragma unroll
        for (int s = 0; s < NSTAGE; s++) {
            mbar_init(sb + s * 8, 1);
            mbar_init(sb + 64 + s * 8, 8);
        }
    }
    __syncthreads();

    if (tid == 0) {
        #pragma unroll
        for (int s = 0; s < NSTAGE; s++) {
            if (s < nk) {
                uint32_t mb = sb + s * 8;
                mbar_expect_tx(mb, STAGE_SZH);
                bulk_g2s(stages + s * STAGE_SZH,        Abase + (size_t)s * ACHH, ACHH, mb);
                bulk_g2s(stages + s * STAGE_SZH + ACHH, Bbase + (size_t)s * BCH,  BCH,  mb);
            }
        }
    }

    float acc[64];
    #pragma unroll
    for (int i = 0; i < 64; i++) acc[i] = 0.0f;

    const int lr = lane & 15;
    const int lc = (lane >> 4) << 3;

    int stage = 0;
    uint32_t par = 0;
    for (int it = 0; it < nk; ++it) {
        mbar_wait(sb + stage * 8, par);

        const uint32_t sA = stages + stage * STAGE_SZH;
        const uint32_t sB = sA + ACHH;

        #pragma unroll
        for (int k2 = 0; k2 < 2; k2++) {
            uint32_t bh[8], bl[8];
            #pragma unroll
            for (int nb = 0; nb < 2; nb++) {
                uint32_t addr = sB + (k2 * 16 + lr) * B_STRIDE
                              + (warp_n + nb * 16 + lc) * 2;
                ldsm4t(&bh[nb * 4], addr);
                ldsm4t(&bl[nb * 4], addr + BHALF);
            }
            #pragma unroll
            for (int mi = 0; mi < 4; mi++) {
                uint32_t ah[4];
                uint32_t addr = sA + (warp_m + mi * 16 + lr) * A_STRIDE
                              + (k2 * 16 + lc) * 2;
                ldsm4(ah, addr);
                #pragma unroll
                for (int ni = 0; ni < 4; ni++) {
                    float* d = acc + (mi * 4 + ni) * 4;
                    mma16816h(d, ah, &bh[ni * 2]);
                    mma16816h(d, ah, &bl[ni * 2]);
                }
            }
        }

        if (lane == 0) mbar_arrive(sb + 64 + stage * 8);

        if (tid == 0 && it + NSTAGE < nk) {
            mbar_wait(sb + 64 + stage * 8, par);
            uint32_t mb = sb + stage * 8;
            mbar_expect_tx(mb, STAGE_SZH);
            bulk_g2s(stages + stage * STAGE_SZH,
                     Abase + (size_t)(it + NSTAGE) * ACHH, ACHH, mb);
            bulk_g2s(stages + stage * STAGE_SZH + ACHH,
                     Bbase + (size_t)(it + NSTAGE) * BCH, BCH, mb);
        }

        if (++stage == NSTAGE) { stage = 0; par ^= 1; }
    }

    // epilogue: bf16-split A-image for the bf16 `out` GEMM
    #pragma unroll
    for (int mi = 0; mi < 4; mi++) {
        #pragma unroll
        for (int ni = 0; ni < 4; ni++) {
            const float* d = acc + (mi * 4 + ni) * 4;
            int r0 = block_row + warp_m + mi * 16 + (lane >> 2);
            int c0 = block_col + warp_n + ni * 8 + (lane & 3) * 2;
            bf16 h0,l0,h1,l1,h2,l2,h3,l3;
            split2(d[0],h0,l0); split2(d[1],h1,l1);
            split2(d[2],h2,l2); split2(d[3],h3,l3);
            writeA2(outA, KCo, r0,     c0, h0, h1, l0, l1);
            writeA2(outA, KCo, r0 + 8, c0, h2, h3, l2, l3);
        }
    }
}

// ---------------- host ------------------------------------------------------
template <typename T>
static T* sym_addr(const void* symbol) {
    void* p = nullptr;
    cudaGetSymbolAddress(&p, symbol);
    return reinterpret_cast<T*>(p);
}

extern "C" void kernel_launch(void* const* d_in, const int* in_sizes, int n_in,
                              void* d_out, int out_size) {
    const float* state  = (const float*)d_in[0];
    const float* action = (const float*)d_in[1];
    const float* task   = (const float*)d_in[2];
    // d_in[3..18]: dead cx branch weights
    const float* W_l1 = (const float*)d_in[19];
    const float* b_l1 = (const float*)d_in[20];
    const float* W_l2 = (const float*)d_in[21];
    const float* b_l2 = (const float*)d_in[22];
    const float* W_l3 = (const float*)d_in[23];
    const float* b_l3 = (const float*)d_in[24];
    const float* W_l4 = (const float*)d_in[25];
    const float* b_l4 = (const float*)d_in[26];
    const float* W_l5 = (const float*)d_in[27];
    const float* b_l5 = (const float*)d_in[28];
    float* out = (float*)d_out;

    cudaFuncSetAttribute(gemm_bulk,
                         cudaFuncAttributeMaxDynamicSharedMemorySize, SMEM_TOT);
    cudaFuncSetAttribute(gemm_bulk64,
                         cudaFuncAttributeMaxDynamicSharedMemorySize, SMEM_TOT64);
    cudaFuncSetAttribute(gemm_g_f16,
                         cudaFuncAttributeMaxDynamicSharedMemorySize, SMEM_TOTH);

    char* ctxH   = sym_addr<char>(g_ctxH);
    char* catA   = sym_addr<char>(g_catA);
    char* w2aA   = sym_addr<char>(g_W2aA);
    char* w3aA   = sym_addr<char>(g_W3aA);
    char* stackB = sym_addr<char>(g_stackB);
    char* e4B    = sym_addr<char>(g_E4B);
    char* gA     = sym_addr<char>(g_GA);
    char* w5B    = sym_addr<char>(g_W5B);

    // 0: ctx' fp16 A-image
    build_ctx<<<BATCH, 256>>>(state, task, action);
    // 1: concat A-image [E1|A2|A3]
    split_cat<<<5248, 512>>>(W_l1, b_l1, W_l2, b_l2, W_l3, b_l3);
    // 2,3: 64-chunk A-images of W2a, W3a
    split_a64<<<2048, 256>>>(W_l2, w2aA, 32);
    split_a64<<<1024, 256>>>(W_l3, w3aA, 32);
    // 4: B-images: W4a into stack chunks 96..127, W5
    {
        SplitArgs sa;
        sa.W[0] = W_l4;
        sa.img[0] = stackB + (size_t)96 * BCH;
        sa.N[0] = 512;  sa.nkB[0] = 128;
        sa.end4[0] = 1024ull * 512 / 4;
        sa.W[1] = W_l5;
        sa.img[1] = w5B;
        sa.N[1] = 1024; sa.nkB[1] = 16;
        sa.end4[1] = sa.end4[0] + 512ull * 1024 / 4;
        split_all<<<(unsigned)((sa.end4[1] + 255) / 256), 256>>>(sa);
    }

    // 5: C34 = W3a@W4a -> stack chunks 64..95
    gemm_bulk64<<<dim3(4, 16), 256, SMEM_TOT64>>>(
        w3aA, stackB + (size_t)96 * BCH, 32, 128, 512,
        nullptr, nullptr, stackB + (size_t)64 * BCH, 128, 0);
    // 6: C234 = W2a@C34 -> stack chunks 0..63
    gemm_bulk64<<<dim3(4, 32), 256, SMEM_TOT64>>>(
        w2aA, stackB + (size_t)64 * BCH, 32, 128, 512,
        nullptr, nullptr, stackB, 128, 0);
    // 7: E4 = [E1|A2|A3]@[C234;C34;W4a] + aug(W4b,b4) -> fp16 split B-image
    gemm_bulk64<<<dim3(4, 82), 256, SMEM_TOT64>>>(
        catA, stackB, 128, 128, 512,
        W_l4 + (size_t)1024 * 512, b_l4, e4B, 164, 1);
    // 8: G = ctx'@E4 (fp16 2-MMA) -> bf16-split A-image
    gemm_g_f16<<<dim3(4, BATCH / 128), 256, SMEM_TOTH>>>(
        ctxH, e4B, 161, 164, 512, gA, 16);
    // 9: out = G@W5 + b5 (bf16 3-MMA)
    gemm_bulk<<<dim3(8, BATCH / 128), 256, SMEM_TOT>>>(
        gA, w5B, 16, 16, 1024, b_l5, out, nullptr, 0);
}

// round 16
// speedup vs baseline: 1.6295x; 1.2123x over previous
#include <cuda_runtime.h>
#include <cuda_bf16.h>
#include <cuda_fp16.h>
#include <cstdint>

// ============================================================================
// Policy_Network — collapsed affine, right-associated chain, fp16-heavy.
//   C34  = W3a@W4a ; C234 = W2a@C34      (bf16 3-MMA, full accuracy)
//   E4   = [E1|A2|A3]@[C234;C34;W4a]+aug (fp16 2-MMA: A plain, B split)
//   G    = ctx'@E4                       (fp16 2-MMA)
//   out  = G@W5 + b5                     (fp16 2-MMA)
// Three independent ~2e-4 fp16-A stages -> total ~3.5e-4 < 1e-3.
// ============================================================================

#define BATCH   8192
#define ADDROWS 5124

typedef __nv_bfloat16 bf16;

// tile image geometry
#define A_STRIDE 80
#define B_STRIDE 272
#define ACH      20480        // 128-row split A chunk (hi+lo)
#define ACH64    10240        // 64-row split A chunk (hi+lo)
#define ACHH     10240        // 128-row single fp16 A chunk
#define ACH64H   5120         // 64-row single fp16 A chunk
#define BCH      17408        // B chunk (hi+lo)
#define AHALF    10240
#define AHALF64  5120
#define BHALF    8704
#define STAGE_SZ64 (ACH64 + BCH)    // 27648 (bf16 64-tile)
#define STAGE_SZE4 (ACH64H + BCH)   // 22528 (fp16 64-tile)
#define STAGE_SZH  (ACHH + BCH)     // 27648 (fp16 128-tile)
#define NSTAGE   3
#define SMEM_TOT64 (128 + NSTAGE * STAGE_SZ64)
#define SMEM_TOTE4 (128 + NSTAGE * STAGE_SZE4)
#define SMEM_TOTH  (128 + NSTAGE * STAGE_SZH)

// ---------------- device scratch: operand images ----------------------------
__device__ __align__(16) char g_ctxH  [(size_t)64 * 161 * ACHH];    // ctx' fp16
__device__ __align__(16) char g_catA  [(size_t)82 * 128 * ACH64H];  // [E1|A2|A3] fp16
__device__ __align__(16) char g_W2aA  [(size_t)32 * 32  * ACH64];   // bf16 split
__device__ __align__(16) char g_W3aA  [(size_t)16 * 32  * ACH64];   // bf16 split
__device__ __align__(16) char g_W4aBbf[(size_t)4  * 32  * BCH];     // bf16 split
__device__ __align__(16) char g_C34Bbf[(size_t)4  * 32  * BCH];     // bf16 split
__device__ __align__(16) char g_stackB[(size_t)4  * 128 * BCH];     // fp16 split
__device__ __align__(16) char g_E4B   [(size_t)4  * 164 * BCH];     // fp16 split
__device__ __align__(16) char g_GA    [(size_t)64 * 16  * ACHH];    // G fp16 single
__device__ __align__(16) char g_W5B   [(size_t)8  * 16  * BCH];     // fp16 split

// ---------------- PTX helpers ----------------------------------------------
__device__ __forceinline__ uint32_t smem_u32(const void* p) {
    uint32_t a;
    asm("{ .reg .u64 t; cvta.to.shared.u64 t, %1; cvt.u32.u64 %0, t; }"
        : "=r"(a) : "l"(p));
    return a;
}
__device__ __forceinline__ void mbar_init(uint32_t m, uint32_t cnt) {
    asm volatile("mbarrier.init.shared.b64 [%0], %1;" :: "r"(m), "r"(cnt) : "memory");
}
__device__ __forceinline__ void mbar_expect_tx(uint32_t m, uint32_t bytes) {
    asm volatile("mbarrier.arrive.expect_tx.shared.b64 _, [%0], %1;"
                 :: "r"(m), "r"(bytes) : "memory");
}
__device__ __forceinline__ void mbar_arrive(uint32_t m) {
    asm volatile("mbarrier.arrive.shared.b64 _, [%0];" :: "r"(m) : "memory");
}
__device__ __forceinline__ void mbar_wait(uint32_t m, uint32_t parity) {
    asm volatile(
        "{\n\t.reg .pred P;\n\t"
        "W_%=:\n\t"
        "mbarrier.try_wait.parity.acquire.cta.shared::cta.b64 P, [%0], %1, 0x989680;\n\t"
        "@!P bra W_%=;\n\t"
        "}" :: "r"(m), "r"(parity) : "memory");
}
__device__ __forceinline__ void bulk_g2s(uint32_t dst, const void* src,
                                         uint32_t bytes, uint32_t mbar) {
    asm volatile(
        "cp.async.bulk.shared::cta.global.mbarrier::complete_tx::bytes [%0], [%1], %2, [%3];"
        :: "r"(dst), "l"(src), "r"(bytes), "r"(mbar) : "memory");
}
__device__ __forceinline__ void ldsm4(uint32_t* r, uint32_t a) {
    asm volatile("ldmatrix.sync.aligned.m8n8.x4.shared.b16 {%0,%1,%2,%3}, [%4];"
        : "=r"(r[0]), "=r"(r[1]), "=r"(r[2]), "=r"(r[3]) : "r"(a));
}
__device__ __forceinline__ void ldsm4t(uint32_t* r, uint32_t a) {
    asm volatile("ldmatrix.sync.aligned.m8n8.x4.trans.shared.b16 {%0,%1,%2,%3}, [%4];"
        : "=r"(r[0]), "=r"(r[1]), "=r"(r[2]), "=r"(r[3]) : "r"(a));
}
__device__ __forceinline__ void mma16816(float* d, const uint32_t* a, const uint32_t* b) {
    asm volatile(
        "mma.sync.aligned.m16n8k16.row.col.f32.bf16.bf16.f32 "
        "{%0,%1,%2,%3}, {%4,%5,%6,%7}, {%8,%9}, {%0,%1,%2,%3};"
        : "+f"(d[0]), "+f"(d[1]), "+f"(d[2]), "+f"(d[3])
        : "r"(a[0]), "r"(a[1]), "r"(a[2]), "r"(a[3]), "r"(b[0]), "r"(b[1]));
}
__device__ __forceinline__ void mma16816h(float* d, const uint32_t* a, const uint32_t* b) {
    asm volatile(
        "mma.sync.aligned.m16n8k16.row.col.f32.f16.f16.f32 "
        "{%0,%1,%2,%3}, {%4,%5,%6,%7}, {%8,%9}, {%0,%1,%2,%3};"
        : "+f"(d[0]), "+f"(d[1]), "+f"(d[2]), "+f"(d[3])
        : "r"(a[0]), "r"(a[1]), "r"(a[2]), "r"(a[3]), "r"(b[0]), "r"(b[1]));
}
__device__ __forceinline__ void split2(float v, bf16& h, bf16& l) {
    h = __float2bfloat16_rn(v);
    l = __float2bfloat16_rn(v - __bfloat162float(h));
}
__device__ __forceinline__ void split2h(float v, __half& h, __half& l) {
    h = __float2half_rn(v);
    l = __float2half_rn(v - __half2float(h));
}

// image writers
__device__ __forceinline__ void writeA2_64(char* img, int nk, int m, int k,
                                           bf16 h0, bf16 h1, bf16 l0, bf16 l1) {
    char* base = img + (size_t)(m >> 6) * ((size_t)nk * ACH64)
               + (size_t)(k >> 5) * ACH64 + (m & 63) * A_STRIDE + (k & 31) * 2;
    *reinterpret_cast<__nv_bfloat162*>(base)           = __nv_bfloat162(h0, h1);
    *reinterpret_cast<__nv_bfloat162*>(base + AHALF64) = __nv_bfloat162(l0, l1);
}
__device__ __forceinline__ void writeAh(char* img, int nk, int m, int k,
                                        __half h0, __half h1) {
    char* base = img + (size_t)(m >> 7) * ((size_t)nk * ACHH)
               + (size_t)(k >> 5) * ACHH + (m & 127) * A_STRIDE + (k & 31) * 2;
    *reinterpret_cast<__half2*>(base) = __half2(h0, h1);
}
__device__ __forceinline__ void writeAh64(char* img, int nk, int m, int k,
                                          __half h0, __half h1) {
    char* base = img + (size_t)(m >> 6) * ((size_t)nk * ACH64H)
               + (size_t)(k >> 5) * ACH64H + (m & 63) * A_STRIDE + (k & 31) * 2;
    *reinterpret_cast<__half2*>(base) = __half2(h0, h1);
}
__device__ __forceinline__ void writeB2(char* img, int nkB, int k, int n,
                                        bf16 h0, bf16 h1, bf16 l0, bf16 l1) {
    char* base = img + (size_t)(n >> 7) * ((size_t)nkB * BCH)
               + (size_t)(k >> 5) * BCH + (k & 31) * B_STRIDE + (n & 127) * 2;
    *reinterpret_cast<__nv_bfloat162*>(base)         = __nv_bfloat162(h0, h1);
    *reinterpret_cast<__nv_bfloat162*>(base + BHALF) = __nv_bfloat162(l0, l1);
}
__device__ __forceinline__ void writeB2h(char* img, int nkB, int k, int n,
                                         __half h0, __half h1, __half l0, __half l1) {
    char* base = img + (size_t)(n >> 7) * ((size_t)nkB * BCH)
               + (size_t)(k >> 5) * BCH + (k & 31) * B_STRIDE + (n & 127) * 2;
    *reinterpret_cast<__half2*>(base)         = __half2(h0, h1);
    *reinterpret_cast<__half2*>(base + BHALF) = __half2(l0, l1);
}

// ---------------- ctx' fp16 A-image build ------------------------------------
__global__ void build_ctx(const float* __restrict__ state,
                          const float* __restrict__ task,
                          const float* __restrict__ action) {
    int r = blockIdx.x, t = threadIdx.x;   // 256 threads
    #pragma unroll 2
    for (int i = t; i < 1024; i += 256) {
        float4 v = reinterpret_cast<const float4*>(state + (size_t)r * 4096)[i];
        writeAh(g_ctxH, 161, r, 4*i,     __float2half_rn(v.x), __float2half_rn(v.y));
        writeAh(g_ctxH, 161, r, 4*i + 2, __float2half_rn(v.z), __float2half_rn(v.w));
    }
    if (t == 0) {
        float4 v = *reinterpret_cast<const float4*>(task + (size_t)r * 4);
        writeAh(g_ctxH, 161, r, 4096, __float2half_rn(v.x), __float2half_rn(v.y));
        writeAh(g_ctxH, 161, r, 4098, __float2half_rn(v.z), __float2half_rn(v.w));
    }
    {
        float4 v = reinterpret_cast<const float4*>(action + (size_t)r * 1024)[t];
        int k = 4100 + 4*t;
        writeAh(g_ctxH, 161, r, k,     __float2half_rn(v.x), __float2half_rn(v.y));
        writeAh(g_ctxH, 161, r, k + 2, __float2half_rn(v.z), __float2half_rn(v.w));
    }
    if (t < 14) {
        __half z = __float2half_rn(0.0f);
        __half one = __float2half_rn(1.0f);
        int k = 5124 + 2*t;
        writeAh(g_ctxH, 161, r, k, (t == 0) ? one : z, z);
    }
}

// ---------------- concat fp16 A-image [E1|A2|A3] (5248 x 4096) --------------
__global__ void split_cat(const float* __restrict__ W1, const float* __restrict__ b1,
                          const float* __restrict__ W2, const float* __restrict__ b2,
                          const float* __restrict__ W3, const float* __restrict__ b3) {
    int m = blockIdx.x;          // 0..5247
    int t = threadIdx.x;         // 512 threads, 8 k each
    int k0 = t * 8;
    const float* src = nullptr;
    if (k0 < 2048) {
        if (m < ADDROWS)       src = W1 + (size_t)m * 2048 + k0;
        else if (m == ADDROWS) src = b1 + k0;
    } else if (k0 < 3072) {
        int kk = k0 - 2048;
        if (m < ADDROWS)       src = W2 + (size_t)(2048 + m) * 1024 + kk;
        else if (m == ADDROWS) src = b2 + kk;
    } else {
        int kk = k0 - 3072;
        if (m < ADDROWS)       src = W3 + (size_t)(1024 + m) * 1024 + kk;
        else if (m == ADDROWS) src = b3 + kk;
    }
    #pragma unroll
    for (int j = 0; j < 2; j++) {
        float4 v = make_float4(0.f, 0.f, 0.f, 0.f);
        if (src) v = *reinterpret_cast<const float4*>(src + j * 4);
        writeAh64(g_catA, 128, m, k0 + j*4,     __float2half_rn(v.x), __float2half_rn(v.y));
        writeAh64(g_catA, 128, m, k0 + j*4 + 2, __float2half_rn(v.z), __float2half_rn(v.w));
    }
}

// ---------------- bf16-split 64-chunk A-image split (K=1024) -----------------
__global__ void split_a64(const float* __restrict__ W, char* img, int nkA) {
    int m = blockIdx.x;
    int k = threadIdx.x * 4;     // 256 threads
    float4 v = *reinterpret_cast<const float4*>(W + (size_t)m * 1024 + k);
    bf16 h0,l0,h1,l1,h2,l2,h3,l3;
    split2(v.x,h0,l0); split2(v.y,h1,l1); split2(v.z,h2,l2); split2(v.w,h3,l3);
    writeA2_64(img, nkA, m, k,     h0, h1, l0, l1);
    writeA2_64(img, nkA, m, k + 2, h2, h3, l2, l3);
}

// ---------------- fused B-image splits ---------------------------------------
// seg0: W4a -> bf16 w4aBbf ; seg1: W4a -> fp16 stack+96 ; seg2: W5 -> fp16 w5B
struct SplitArgs {
    const float* W[3];
    char* img[3];
    int N[3];
    int nkB[3];
    int fmt[3];                  // 0 = bf16 split, 1 = fp16 split
    unsigned long long end4[3];
};

__global__ void split_all(SplitArgs a) {
    unsigned long long e = (unsigned long long)blockIdx.x * 256 + threadIdx.x;
    unsigned long long start = 0;
    #pragma unroll
    for (int s = 0; s < 3; s++) {
        if (e < a.end4[s]) {
            unsigned long long base = (e - start) * 4;
            int N = a.N[s];
            int k = (int)(base / N), n = (int)(base % N);
            float4 v = *reinterpret_cast<const float4*>(a.W[s] + base);
            if (a.fmt[s]) {
                __half h0,l0,h1,l1,h2,l2,h3,l3;
                split2h(v.x,h0,l0); split2h(v.y,h1,l1);
                split2h(v.z,h2,l2); split2h(v.w,h3,l3);
                writeB2h(a.img[s], a.nkB[s], k, n,     h0, h1, l0, l1);
                writeB2h(a.img[s], a.nkB[s], k, n + 2, h2, h3, l2, l3);
            } else {
                bf16 h0,l0,h1,l1,h2,l2,h3,l3;
                split2(v.x,h0,l0); split2(v.y,h1,l1);
                split2(v.z,h2,l2); split2(v.w,h3,l3);
                writeB2(a.img[s], a.nkB[s], k, n,     h0, h1, l0, l1);
                writeB2(a.img[s], a.nkB[s], k, n + 2, h2, h3, l2, l3);
            }
            return;
        }
        start = a.end4[s];
    }
}

// ---------------- common epilogue addend ------------------------------------
__device__ __forceinline__ float addval(const float* AddW, const float* Addb,
                                        int r, int c, int N) {
    if (AddW && r < ADDROWS) return AddW[(size_t)r * N + c];
    if (Addb && r == ADDROWS) return Addb[c];
    return 0.0f;
}

// ---------------- 64-tile bf16 3-MMA GEMM (micro chain; dual-format out) ----
__global__ __launch_bounds__(256, 2)
void gemm_bulk64(const char* __restrict__ Aimg, const char* __restrict__ Bimg,
                 int nk, int nkB, int N,
                 char* __restrict__ outBbf, int KCbf,
                 char* __restrict__ outBh,  int KCh) {
    extern __shared__ char smem_raw[];
    const uint32_t sb = smem_u32(smem_raw);
    const uint32_t stages = sb + 128;

    const int tid  = threadIdx.x;
    const int wid  = tid >> 5;
    const int lane = tid & 31;
    const int warp_m = (wid & 1) * 32;
    const int warp_n = (wid >> 1) * 32;
    const int block_row = blockIdx.y * 64;
    const int block_col = blockIdx.x * 128;

    const char* Abase = Aimg + (size_t)blockIdx.y * ((size_t)nk  * ACH64);
    const char* Bbase = Bimg + (size_t)blockIdx.x * ((size_t)nkB * BCH);

    if (tid == 0) {
        #pragma unroll
        for (int s = 0; s < NSTAGE; s++) {
            mbar_init(sb + s * 8, 1);
            mbar_init(sb + 64 + s * 8, 8);
        }
    }
    __syncthreads();

    if (tid == 0) {
        #pragma unroll
        for (int s = 0; s < NSTAGE; s++) {
            if (s < nk) {
                uint32_t mb = sb + s * 8;
                mbar_expect_tx(mb, STAGE_SZ64);
                bulk_g2s(stages + s * STAGE_SZ64,         Abase + (size_t)s * ACH64, ACH64, mb);
                bulk_g2s(stages + s * STAGE_SZ64 + ACH64, Bbase + (size_t)s * BCH,   BCH,   mb);
            }
        }
    }

    float acc[32];
    #pragma unroll
    for (int i = 0; i < 32; i++) acc[i] = 0.0f;

    const int lr = lane & 15;
    const int lc = (lane >> 4) << 3;

    int stage = 0;
    uint32_t par = 0;
    for (int it = 0; it < nk; ++it) {
        mbar_wait(sb + stage * 8, par);

        const uint32_t sA = stages + stage * STAGE_SZ64;
        const uint32_t sB = sA + ACH64;

        #pragma unroll
        for (int k2 = 0; k2 < 2; k2++) {
            uint32_t bh[8], bl[8];
            #pragma unroll
            for (int nb = 0; nb < 2; nb++) {
                uint32_t addr = sB + (k2 * 16 + lr) * B_STRIDE
                              + (warp_n + nb * 16 + lc) * 2;
                ldsm4t(&bh[nb * 4], addr);
                ldsm4t(&bl[nb * 4], addr + BHALF);
            }
            #pragma unroll
            for (int mi = 0; mi < 2; mi++) {
                uint32_t ah[4], al[4];
                uint32_t addr = sA + (warp_m + mi * 16 + lr) * A_STRIDE
                              + (k2 * 16 + lc) * 2;
                ldsm4(ah, addr);
                ldsm4(al, addr + AHALF64);
                #pragma unroll
                for (int ni = 0; ni < 4; ni++) {
                    float* d = acc + (mi * 4 + ni) * 4;
                    mma16816(d, ah, &bh[ni * 2]);
                    mma16816(d, ah, &bl[ni * 2]);
                    mma16816(d, al, &bh[ni * 2]);
                }
            }
        }

        if (lane == 0) mbar_arrive(sb + 64 + stage * 8);

        if (tid == 0 && it + NSTAGE < nk) {
            mbar_wait(sb + 64 + stage * 8, par);
            uint32_t mb = sb + stage * 8;
            mbar_expect_tx(mb, STAGE_SZ64);
            bulk_g2s(stages + stage * STAGE_SZ64,
                     Abase + (size_t)(it + NSTAGE) * ACH64, ACH64, mb);
            bulk_g2s(stages + stage * STAGE_SZ64 + ACH64,
                     Bbase + (size_t)(it + NSTAGE) * BCH, BCH, mb);
        }

        if (++stage == NSTAGE) { stage = 0; par ^= 1; }
    }

    #pragma unroll
    for (int mi = 0; mi < 2; mi++) {
        #pragma unroll
        for (int ni = 0; ni < 4; ni++) {
            const float* d = acc + (mi * 4 + ni) * 4;
            int r0 = block_row + warp_m + mi * 16 + (lane >> 2);
            int c0 = block_col + warp_n + ni * 8 + (lane & 3) * 2;
            if (outBbf) {
                bf16 h0,l0,h1,l1,h2,l2,h3,l3;
                split2(d[0],h0,l0); split2(d[1],h1,l1);
                split2(d[2],h2,l2); split2(d[3],h3,l3);
                writeB2(outBbf, KCbf, r0,     c0, h0, h1, l0, l1);
                writeB2(outBbf, KCbf, r0 + 8, c0, h2, h3, l2, l3);
            }
            if (outBh) {
                __half h0,l0,h1,l1,h2,l2,h3,l3;
                split2h(d[0],h0,l0); split2h(d[1],h1,l1);
                split2h(d[2],h2,l2); split2h(d[3],h3,l3);
                writeB2h(outBh, KCh, r0,     c0, h0, h1, l0, l1);
                writeB2h(outBh, KCh, r0 + 8, c0, h2, h3, l2, l3);
            }
        }
    }
}

// ---------------- 64-tile fp16 2-MMA GEMM (E4) -------------------------------
__global__ __launch_bounds__(256, 2)
void gemm_e4_f16(const char* __restrict__ Aimg, const char* __restrict__ Bimg,
                 int nk, int nkB, int N,
                 const float* __restrict__ AddW, const float* __restrict__ Addb,
                 char* __restrict__ outBh, int KCh) {
    extern __shared__ char smem_raw[];
    const uint32_t sb = smem_u32(smem_raw);
    const uint32_t stages = sb + 128;

    const int tid  = threadIdx.x;
    const int wid  = tid >> 5;
    const int lane = tid & 31;
    const int warp_m = (wid & 1) * 32;
    const int warp_n = (wid >> 1) * 32;
    const int block_row = blockIdx.y * 64;
    const int block_col = blockIdx.x * 128;

    const char* Abase = Aimg + (size_t)blockIdx.y * ((size_t)nk  * ACH64H);
    const char* Bbase = Bimg + (size_t)blockIdx.x * ((size_t)nkB * BCH);

    if (tid == 0) {
        #pragma unroll
        for (int s = 0; s < NSTAGE; s++) {
            mbar_init(sb + s * 8, 1);
            mbar_init(sb + 64 + s * 8, 8);
        }
    }
    __syncthreads();

    if (tid == 0) {
        #pragma unroll
        for (int s = 0; s < NSTAGE; s++) {
            if (s < nk) {
                uint32_t mb = sb + s * 8;
                mbar_expect_tx(mb, STAGE_SZE4);
                bulk_g2s(stages + s * STAGE_SZE4,          Abase + (size_t)s * ACH64H, ACH64H, mb);
                bulk_g2s(stages + s * STAGE_SZE4 + ACH64H, Bbase + (size_t)s * BCH,    BCH,    mb);
            }
        }
    }

    float acc[32];
    #pragma unroll
    for (int i = 0; i < 32; i++) acc[i] = 0.0f;

    const int lr = lane & 15;
    const int lc = (lane >> 4) << 3;

    int stage = 0;
    uint32_t par = 0;
    for (int it = 0; it < nk; ++it) {
        mbar_wait(sb + stage * 8, par);

        const uint32_t sA = stages + stage * STAGE_SZE4;
        const uint32_t sB = sA + ACH64H;

        #pragma unroll
        for (int k2 = 0; k2 < 2; k2++) {
            uint32_t bh[8], bl[8];
            #pragma unroll
            for (int nb = 0; nb < 2; nb++) {
                uint32_t addr = sB + (k2 * 16 + lr) * B_STRIDE
                              + (warp_n + nb * 16 + lc) * 2;
                ldsm4t(&bh[nb * 4], addr);
                ldsm4t(&bl[nb * 4], addr + BHALF);
            }
            #pragma unroll
            for (int mi = 0; mi < 2; mi++) {
                uint32_t ah[4];
                uint32_t addr = sA + (warp_m + mi * 16 + lr) * A_STRIDE
                              + (k2 * 16 + lc) * 2;
                ldsm4(ah, addr);
                #pragma unroll
                for (int ni = 0; ni < 4; ni++) {
                    float* d = acc + (mi * 4 + ni) * 4;
                    mma16816h(d, ah, &bh[ni * 2]);
                    mma16816h(d, ah, &bl[ni * 2]);
                }
            }
        }

        if (lane == 0) mbar_arrive(sb + 64 + stage * 8);

        if (tid == 0 && it + NSTAGE < nk) {
            mbar_wait(sb + 64 + stage * 8, par);
            uint32_t mb = sb + stage * 8;
            mbar_expect_tx(mb, STAGE_SZE4);
            bulk_g2s(stages + stage * STAGE_SZE4,
                     Abase + (size_t)(it + NSTAGE) * ACH64H, ACH64H, mb);
            bulk_g2s(stages + stage * STAGE_SZE4 + ACH64H,
                     Bbase + (size_t)(it + NSTAGE) * BCH, BCH, mb);
        }

        if (++stage == NSTAGE) { stage = 0; par ^= 1; }
    }

    #pragma unroll
    for (int mi = 0; mi < 2; mi++) {
        #pragma unroll
        for (int ni = 0; ni < 4; ni++) {
            const float* d = acc + (mi * 4 + ni) * 4;
            int r0 = block_row + warp_m + mi * 16 + (lane >> 2);
            int c0 = block_col + warp_n + ni * 8 + (lane & 3) * 2;
            float v00 = d[0] + addval(AddW, Addb, r0,     c0,     N);
            float v01 = d[1] + addval(AddW, Addb, r0,     c0 + 1, N);
            float v10 = d[2] + addval(AddW, Addb, r0 + 8, c0,     N);
            float v11 = d[3] + addval(AddW, Addb, r0 + 8, c0 + 1, N);
            __half h0,l0,h1,l1,h2,l2,h3,l3;
            split2h(v00,h0,l0); split2h(v01,h1,l1);
            split2h(v10,h2,l2); split2h(v11,h3,l3);
            writeB2h(outBh, KCh, r0,     c0, h0, h1, l0, l1);
            writeB2h(outBh, KCh, r0 + 8, c0, h2, h3, l2, l3);
        }
    }
}

// ---------------- 128-tile fp16 2-MMA GEMM (G and out) -----------------------
__global__ __launch_bounds__(256, 2)
void gemm_f16(const char* __restrict__ Aimg, const char* __restrict__ Bimg,
              int nk, int nkB, int N,
              const float* __restrict__ BiasN,
              float* __restrict__ Cf,
              char* __restrict__ outAh, int KCo) {
    extern __shared__ char smem_raw[];
    const uint32_t sb = smem_u32(smem_raw);
    const uint32_t stages = sb + 128;

    const int tid  = threadIdx.x;
    const int wid  = tid >> 5;
    const int lane = tid & 31;
    const int warp_m = (wid & 1) * 64;
    const int warp_n = (wid >> 1) * 32;
    const int block_row = blockIdx.y * 128;
    const int block_col = blockIdx.x * 128;

    const char* Abase = Aimg + (size_t)blockIdx.y * ((size_t)nk  * ACHH);
    const char* Bbase = Bimg + (size_t)blockIdx.x * ((size_t)nkB * BCH);

    if (tid == 0) {
        #pragma unroll
        for (int s = 0; s < NSTAGE; s++) {
            mbar_init(sb + s * 8, 1);
            mbar_init(sb + 64 + s * 8, 8);
        }
    }
    __syncthreads();

    if (tid == 0) {
        #pragma unroll
        for (int s = 0; s < NSTAGE; s++) {
            if (s < nk) {
                uint32_t mb = sb + s * 8;
                mbar_expect_tx(mb, STAGE_SZH);
                bulk_g2s(stages + s * STAGE_SZH,        Abase + (size_t)s * ACHH, ACHH, mb);
                bulk_g2s(stages + s * STAGE_SZH + ACHH, Bbase + (size_t)s * BCH,  BCH,  mb);
            }
        }
    }

    float acc[64];
    #pragma unroll
    for (int i = 0; i < 64; i++) acc[i] = 0.0f;

    const int lr = lane & 15;
    const int lc = (lane >> 4) << 3;

    int stage = 0;
    uint32_t par = 0;
    for (int it = 0; it < nk; ++it) {
        mbar_wait(sb + stage * 8, par);

        const uint32_t sA = stages + stage * STAGE_SZH;
        const uint32_t sB = sA + ACHH;

        #pragma unroll
        for (int k2 = 0; k2 < 2; k2++) {
            uint32_t bh[8], bl[8];
            #pragma unroll
            for (int nb = 0; nb < 2; nb++) {
                uint32_t addr = sB + (k2 * 16 + lr) * B_STRIDE
                              + (warp_n + nb * 16 + lc) * 2;
                ldsm4t(&bh[nb * 4], addr);
                ldsm4t(&bl[nb * 4], addr + BHALF);
            }
            #pragma unroll
            for (int mi = 0; mi < 4; mi++) {
                uint32_t ah[4];
                uint32_t addr = sA + (warp_m + mi * 16 + lr) * A_STRIDE
                              + (k2 * 16 + lc) * 2;
                ldsm4(ah, addr);
                #pragma unroll
                for (int ni = 0; ni < 4; ni++) {
                    float* d = acc + (mi * 4 + ni) * 4;
                    mma16816h(d, ah, &bh[ni * 2]);
                    mma16816h(d, ah, &bl[ni * 2]);
                }
            }
        }

        if (lane == 0) mbar_arrive(sb + 64 + stage * 8);

        if (tid == 0 && it + NSTAGE < nk) {
            mbar_wait(sb + 64 + stage * 8, par);
            uint32_t mb = sb + stage * 8;
            mbar_expect_tx(mb, STAGE_SZH);
            bulk_g2s(stages + stage * STAGE_SZH,
                     Abase + (size_t)(it + NSTAGE) * ACHH, ACHH, mb);
            bulk_g2s(stages + stage * STAGE_SZH + ACHH,
                     Bbase + (size_t)(it + NSTAGE) * BCH, BCH, mb);
        }

        if (++stage == NSTAGE) { stage = 0; par ^= 1; }
    }

    #pragma unroll
    for (int mi = 0; mi < 4; mi++) {
        #pragma unroll
        for (int ni = 0; ni < 4; ni++) {
            const float* d = acc + (mi * 4 + ni) * 4;
            int r0 = block_row + warp_m + mi * 16 + (lane >> 2);
            int c0 = block_col + warp_n + ni * 8 + (lane & 3) * 2;
            if (Cf) {
                float b0 = BiasN ? BiasN[c0]     : 0.0f;
                float b1 = BiasN ? BiasN[c0 + 1] : 0.0f;
                *reinterpret_cast<float2*>(Cf + (size_t)r0 * N + c0) =
                    make_float2(d[0] + b0, d[1] + b1);
                *reinterpret_cast<float2*>(Cf + (size_t)(r0 + 8) * N + c0) =
                    make_float2(d[2] + b0, d[3] + b1);
            } else {
                writeAh(outAh, KCo, r0,     c0,
                        __float2half_rn(d[0]), __float2half_rn(d[1]));
                writeAh(outAh, KCo, r0 + 8, c0,
                        __float2half_rn(d[2]), __float2half_rn(d[3]));
            }
        }
    }
}

// ---------------- host ------------------------------------------------------
template <typename T>
static T* sym_addr(const void* symbol) {
    void* p = nullptr;
    cudaGetSymbolAddress(&p, symbol);
    return reinterpret_cast<T*>(p);
}

extern "C" void kernel_launch(void* const* d_in, const int* in_sizes, int n_in,
                              void* d_out, int out_size) {
    const float* state  = (const float*)d_in[0];
    const float* action = (const float*)d_in[1];
    const float* task   = (const float*)d_in[2];
    // d_in[3..18]: dead cx branch weights
    const float* W_l1 = (const float*)d_in[19];
    const float* b_l1 = (const float*)d_in[20];
    const float* W_l2 = (const float*)d_in[21];
    const float* b_l2 = (const float*)d_in[22];
    const float* W_l3 = (const float*)d_in[23];
    const float* b_l3 = (const float*)d_in[24];
    const float* W_l4 = (const float*)d_in[25];
    const float* b_l4 = (const float*)d_in[26];
    const float* W_l5 = (const float*)d_in[27];
    const float* b_l5 = (const float*)d_in[28];
    float* out = (float*)d_out;

    cudaFuncSetAttribute(gemm_bulk64,
                         cudaFuncAttributeMaxDynamicSharedMemorySize, SMEM_TOT64);
    cudaFuncSetAttribute(gemm_e4_f16,
                         cudaFuncAttributeMaxDynamicSharedMemorySize, SMEM_TOTE4);
    cudaFuncSetAttribute(gemm_f16,
                         cudaFuncAttributeMaxDynamicSharedMemorySize, SMEM_TOTH);

    char* ctxH   = sym_addr<char>(g_ctxH);
    char* catA   = sym_addr<char>(g_catA);
    char* w2aA   = sym_addr<char>(g_W2aA);
    char* w3aA   = sym_addr<char>(g_W3aA);
    char* w4aBbf = sym_addr<char>(g_W4aBbf);
    char* c34Bbf = sym_addr<char>(g_C34Bbf);
    char* stackB = sym_addr<char>(g_stackB);
    char* e4B    = sym_addr<char>(g_E4B);
    char* gA     = sym_addr<char>(g_GA);
    char* w5B    = sym_addr<char>(g_W5B);

    // 0: ctx' fp16 A-image
    build_ctx<<<BATCH, 256>>>(state, task, action);
    // 1: concat fp16 A-image [E1|A2|A3]
    split_cat<<<5248, 512>>>(W_l1, b_l1, W_l2, b_l2, W_l3, b_l3);
    // 2,3: bf16-split A-images of W2a, W3a (micro chain keeps full accuracy)
    split_a64<<<2048, 256>>>(W_l2, w2aA, 32);
    split_a64<<<1024, 256>>>(W_l3, w3aA, 32);
    // 4: B-images: W4a (bf16 + fp16 copies), W5 (fp16)
    {
        SplitArgs sa;
        sa.W[0] = W_l4; sa.img[0] = w4aBbf;               sa.N[0] = 512;  sa.nkB[0] = 32;  sa.fmt[0] = 0;
        sa.end4[0] = 1024ull * 512 / 4;
        sa.W[1] = W_l4; sa.img[1] = stackB + (size_t)96 * BCH; sa.N[1] = 512; sa.nkB[1] = 128; sa.fmt[1] = 1;
        sa.end4[1] = sa.end4[0] + 1024ull * 512 / 4;
        sa.W[2] = W_l5; sa.img[2] = w5B;                  sa.N[2] = 1024; sa.nkB[2] = 16;  sa.fmt[2] = 1;
        sa.end4[2] = sa.end4[1] + 512ull * 1024 / 4;
        split_all<<<(unsigned)((sa.end4[2] + 255) / 256), 256>>>(sa);
    }

    // 5: C34 = W3a@W4a -> bf16 c34Bbf AND fp16 stack chunks 64..95
    gemm_bulk64<<<dim3(4, 16), 256, SMEM_TOT64>>>(
        w3aA, w4aBbf, 32, 32, 512,
        c34Bbf, 32, stackB + (size_t)64 * BCH, 128);
    // 6: C234 = W2a@C34 -> fp16 stack chunks 0..63
    gemm_bulk64<<<dim3(4, 32), 256, SMEM_TOT64>>>(
        w2aA, c34Bbf, 32, 32, 512,
        nullptr, 0, stackB, 128);
    // 7: E4 = [E1|A2|A3]@[C234;C34;W4a] + aug(W4b,b4) -> fp16 split B-image
    gemm_e4_f16<<<dim3(4, 82), 256, SMEM_TOTE4>>>(
        catA, stackB, 128, 128, 512,
        W_l4 + (size_t)1024 * 512, b_l4, e4B, 164);
    // 8: G = ctx'@E4 (fp16 2-MMA) -> fp16 single A-image
    gemm_f16<<<dim3(4, BATCH / 128), 256, SMEM_TOTH>>>(
        ctxH, e4B, 161, 164, 512, nullptr, nullptr, gA, 16);
    // 9: out = G@W5 + b5 (fp16 2-MMA)
    gemm_f16<<<dim3(8, BATCH / 128), 256, SMEM_TOTH>>>(
        gA, w5B, 16, 16, 1024, b_l5, out, nullptr, 0);
}

// round 17
// speedup vs baseline: 2.2207x; 1.3628x over previous
#include <cuda_runtime.h>
#include <cuda_bf16.h>
#include <cuda_fp16.h>
#include <cstdint>

// ============================================================================
// Policy_Network — collapsed affine, right-associated chain, plain-fp16 GEMMs.
//   C34  = W3a@W4a ; C234 = W2a@C34      (bf16 3-MMA, full accuracy)
//   E4   = [E1|A2|A3]@[C234;C34;W4a]+aug (fp16 1-MMA, both operands plain)
//   G    = ctx'@E4                       (fp16 1-MMA)
//   out  = G@W5 + b5                     (fp16 1-MMA)
// Six independent ~1.7e-4 fp16 operand quantizations -> ~4.2e-4 < 1e-3.
// ============================================================================

#define BATCH   8192
#define ADDROWS 5124

typedef __nv_bfloat16 bf16;

// tile image geometry
#define A_STRIDE 80
#define B_STRIDE 272
#define ACH64    10240        // 64-row split A chunk (hi+lo), bf16
#define ACHH     10240        // 128-row single fp16 A chunk
#define ACH64H   5120         // 64-row single fp16 A chunk
#define BCH      17408        // split B chunk (hi+lo)
#define BCHH     8704         // single fp16 B chunk
#define AHALF64  5120
#define BHALF    8704
#define STAGE_SZ64 (ACH64 + BCH)     // 27648 (bf16 micro)
#define STAGE_SZE4 (ACH64H + BCHH)   // 13824 (fp16 64-tile)
#define STAGE_SZH  (ACHH + BCHH)     // 18944 (fp16 128-tile)
#define NSTAGE   3
#define SMEM_TOT64 (128 + NSTAGE * STAGE_SZ64)
#define SMEM_TOTE4 (128 + NSTAGE * STAGE_SZE4)
#define SMEM_TOTH  (128 + NSTAGE * STAGE_SZH)

// ---------------- device scratch: operand images ----------------------------
__device__ __align__(16) char g_ctxH  [(size_t)64 * 161 * ACHH];    // ctx' fp16
__device__ __align__(16) char g_catA  [(size_t)82 * 128 * ACH64H];  // [E1|A2|A3] fp16
__device__ __align__(16) char g_W2aA  [(size_t)32 * 32  * ACH64];   // bf16 split
__device__ __align__(16) char g_W3aA  [(size_t)16 * 32  * ACH64];   // bf16 split
__device__ __align__(16) char g_W4aBbf[(size_t)4  * 32  * BCH];     // bf16 split
__device__ __align__(16) char g_C34Bbf[(size_t)4  * 32  * BCH];     // bf16 split
__device__ __align__(16) char g_stackB[(size_t)4  * 128 * BCHH];    // fp16 single
__device__ __align__(16) char g_E4B   [(size_t)4  * 164 * BCHH];    // fp16 single
__device__ __align__(16) char g_GA    [(size_t)64 * 16  * ACHH];    // G fp16 single
__device__ __align__(16) char g_W5B   [(size_t)8  * 16  * BCHH];    // fp16 single

// ---------------- PTX helpers ----------------------------------------------
__device__ __forceinline__ uint32_t smem_u32(const void* p) {
    uint32_t a;
    asm("{ .reg .u64 t; cvta.to.shared.u64 t, %1; cvt.u32.u64 %0, t; }"
        : "=r"(a) : "l"(p));
    return a;
}
__device__ __forceinline__ void mbar_init(uint32_t m, uint32_t cnt) {
    asm volatile("mbarrier.init.shared.b64 [%0], %1;" :: "r"(m), "r"(cnt) : "memory");
}
__device__ __forceinline__ void mbar_expect_tx(uint32_t m, uint32_t bytes) {
    asm volatile("mbarrier.arrive.expect_tx.shared.b64 _, [%0], %1;"
                 :: "r"(m), "r"(bytes) : "memory");
}
__device__ __forceinline__ void mbar_arrive(uint32_t m) {
    asm volatile("mbarrier.arrive.shared.b64 _, [%0];" :: "r"(m) : "memory");
}
__device__ __forceinline__ void mbar_wait(uint32_t m, uint32_t parity) {
    asm volatile(
        "{\n\t.reg .pred P;\n\t"
        "W_%=:\n\t"
        "mbarrier.try_wait.parity.acquire.cta.shared::cta.b64 P, [%0], %1, 0x989680;\n\t"
        "@!P bra W_%=;\n\t"
        "}" :: "r"(m), "r"(parity) : "memory");
}
__device__ __forceinline__ void bulk_g2s(uint32_t dst, const void* src,
                                         uint32_t bytes, uint32_t mbar) {
    asm volatile(
        "cp.async.bulk.shared::cta.global.mbarrier::complete_tx::bytes [%0], [%1], %2, [%3];"
        :: "r"(dst), "l"(src), "r"(bytes), "r"(mbar) : "memory");
}
__device__ __forceinline__ void ldsm4(uint32_t* r, uint32_t a) {
    asm volatile("ldmatrix.sync.aligned.m8n8.x4.shared.b16 {%0,%1,%2,%3}, [%4];"
        : "=r"(r[0]), "=r"(r[1]), "=r"(r[2]), "=r"(r[3]) : "r"(a));
}
__device__ __forceinline__ void ldsm4t(uint32_t* r, uint32_t a) {
    asm volatile("ldmatrix.sync.aligned.m8n8.x4.trans.shared.b16 {%0,%1,%2,%3}, [%4];"
        : "=r"(r[0]), "=r"(r[1]), "=r"(r[2]), "=r"(r[3]) : "r"(a));
}
__device__ __forceinline__ void mma16816(float* d, const uint32_t* a, const uint32_t* b) {
    asm volatile(
        "mma.sync.aligned.m16n8k16.row.col.f32.bf16.bf16.f32 "
        "{%0,%1,%2,%3}, {%4,%5,%6,%7}, {%8,%9}, {%0,%1,%2,%3};"
        : "+f"(d[0]), "+f"(d[1]), "+f"(d[2]), "+f"(d[3])
        : "r"(a[0]), "r"(a[1]), "r"(a[2]), "r"(a[3]), "r"(b[0]), "r"(b[1]));
}
__device__ __forceinline__ void mma16816h(float* d, const uint32_t* a, const uint32_t* b) {
    asm volatile(
        "mma.sync.aligned.m16n8k16.row.col.f32.f16.f16.f32 "
        "{%0,%1,%2,%3}, {%4,%5,%6,%7}, {%8,%9}, {%0,%1,%2,%3};"
        : "+f"(d[0]), "+f"(d[1]), "+f"(d[2]), "+f"(d[3])
        : "r"(a[0]), "r"(a[1]), "r"(a[2]), "r"(a[3]), "r"(b[0]), "r"(b[1]));
}
__device__ __forceinline__ void split2(float v, bf16& h, bf16& l) {
    h = __float2bfloat16_rn(v);
    l = __float2bfloat16_rn(v - __bfloat162float(h));
}

// image writers
__device__ __forceinline__ void writeA2_64(char* img, int nk, int m, int k,
                                           bf16 h0, bf16 h1, bf16 l0, bf16 l1) {
    char* base = img + (size_t)(m >> 6) * ((size_t)nk * ACH64)
               + (size_t)(k >> 5) * ACH64 + (m & 63) * A_STRIDE + (k & 31) * 2;
    *reinterpret_cast<__nv_bfloat162*>(base)           = __nv_bfloat162(h0, h1);
    *reinterpret_cast<__nv_bfloat162*>(base + AHALF64) = __nv_bfloat162(l0, l1);
}
__device__ __forceinline__ void writeAh(char* img, int nk, int m, int k,
                                        __half h0, __half h1) {
    char* base = img + (size_t)(m >> 7) * ((size_t)nk * ACHH)
               + (size_t)(k >> 5) * ACHH + (m & 127) * A_STRIDE + (k & 31) * 2;
    *reinterpret_cast<__half2*>(base) = __half2(h0, h1);
}
__device__ __forceinline__ void writeAh64(char* img, int nk, int m, int k,
                                          __half h0, __half h1) {
    char* base = img + (size_t)(m >> 6) * ((size_t)nk * ACH64H)
               + (size_t)(k >> 5) * ACH64H + (m & 63) * A_STRIDE + (k & 31) * 2;
    *reinterpret_cast<__half2*>(base) = __half2(h0, h1);
}
__device__ __forceinline__ void writeB2(char* img, int nkB, int k, int n,
                                        bf16 h0, bf16 h1, bf16 l0, bf16 l1) {
    char* base = img + (size_t)(n >> 7) * ((size_t)nkB * BCH)
               + (size_t)(k >> 5) * BCH + (k & 31) * B_STRIDE + (n & 127) * 2;
    *reinterpret_cast<__nv_bfloat162*>(base)         = __nv_bfloat162(h0, h1);
    *reinterpret_cast<__nv_bfloat162*>(base + BHALF) = __nv_bfloat162(l0, l1);
}
__device__ __forceinline__ void writeB1h(char* img, int nkB, int k, int n,
                                         __half h0, __half h1) {
    char* base = img + (size_t)(n >> 7) * ((size_t)nkB * BCHH)
               + (size_t)(k >> 5) * BCHH + (k & 31) * B_STRIDE + (n & 127) * 2;
    *reinterpret_cast<__half2*>(base) = __half2(h0, h1);
}

// ---------------- ctx' fp16 A-image build ------------------------------------
__global__ void build_ctx(const float* __restrict__ state,
                          const float* __restrict__ task,
                          const float* __restrict__ action) {
    int r = blockIdx.x, t = threadIdx.x;   // 256 threads
    #pragma unroll 2
    for (int i = t; i < 1024; i += 256) {
        float4 v = reinterpret_cast<const float4*>(state + (size_t)r * 4096)[i];
        writeAh(g_ctxH, 161, r, 4*i,     __float2half_rn(v.x), __float2half_rn(v.y));
        writeAh(g_ctxH, 161, r, 4*i + 2, __float2half_rn(v.z), __float2half_rn(v.w));
    }
    if (t == 0) {
        float4 v = *reinterpret_cast<const float4*>(task + (size_t)r * 4);
        writeAh(g_ctxH, 161, r, 4096, __float2half_rn(v.x), __float2half_rn(v.y));
        writeAh(g_ctxH, 161, r, 4098, __float2half_rn(v.z), __float2half_rn(v.w));
    }
    {
        float4 v = reinterpret_cast<const float4*>(action + (size_t)r * 1024)[t];
        int k = 4100 + 4*t;
        writeAh(g_ctxH, 161, r, k,     __float2half_rn(v.x), __float2half_rn(v.y));
        writeAh(g_ctxH, 161, r, k + 2, __float2half_rn(v.z), __float2half_rn(v.w));
    }
    if (t < 14) {
        __half z = __float2half_rn(0.0f);
        __half one = __float2half_rn(1.0f);
        int k = 5124 + 2*t;
        writeAh(g_ctxH, 161, r, k, (t == 0) ? one : z, z);
    }
}

// ---------------- concat fp16 A-image [E1|A2|A3] (5248 x 4096) --------------
__global__ void split_cat(const float* __restrict__ W1, const float* __restrict__ b1,
                          const float* __restrict__ W2, const float* __restrict__ b2,
                          const float* __restrict__ W3, const float* __restrict__ b3) {
    int m = blockIdx.x;          // 0..5247
    int t = threadIdx.x;         // 512 threads, 8 k each
    int k0 = t * 8;
    const float* src = nullptr;
    if (k0 < 2048) {
        if (m < ADDROWS)       src = W1 + (size_t)m * 2048 + k0;
        else if (m == ADDROWS) src = b1 + k0;
    } else if (k0 < 3072) {
        int kk = k0 - 2048;
        if (m < ADDROWS)       src = W2 + (size_t)(2048 + m) * 1024 + kk;
        else if (m == ADDROWS) src = b2 + kk;
    } else {
        int kk = k0 - 3072;
        if (m < ADDROWS)       src = W3 + (size_t)(1024 + m) * 1024 + kk;
        else if (m == ADDROWS) src = b3 + kk;
    }
    #pragma unroll
    for (int j = 0; j < 2; j++) {
        float4 v = make_float4(0.f, 0.f, 0.f, 0.f);
        if (src) v = *reinterpret_cast<const float4*>(src + j * 4);
        writeAh64(g_catA, 128, m, k0 + j*4,     __float2half_rn(v.x), __float2half_rn(v.y));
        writeAh64(g_catA, 128, m, k0 + j*4 + 2, __float2half_rn(v.z), __float2half_rn(v.w));
    }
}

// ---------------- bf16-split 64-chunk A-image split (K=1024) -----------------
__global__ void split_a64(const float* __restrict__ W, char* img, int nkA) {
    int m = blockIdx.x;
    int k = threadIdx.x * 4;     // 256 threads
    float4 v = *reinterpret_cast<const float4*>(W + (size_t)m * 1024 + k);
    bf16 h0,l0,h1,l1,h2,l2,h3,l3;
    split2(v.x,h0,l0); split2(v.y,h1,l1); split2(v.z,h2,l2); split2(v.w,h3,l3);
    writeA2_64(img, nkA, m, k,     h0, h1, l0, l1);
    writeA2_64(img, nkA, m, k + 2, h2, h3, l2, l3);
}

// ---------------- fused B-image splits ---------------------------------------
// seg0: W4a -> bf16 split w4aBbf ; seg1: W4a -> fp16 single stack+96 ;
// seg2: W5 -> fp16 single w5B
struct SplitArgs {
    const float* W[3];
    char* img[3];
    int N[3];
    int nkB[3];
    int fmt[3];                  // 0 = bf16 split, 1 = fp16 single
    unsigned long long end4[3];
};

__global__ void split_all(SplitArgs a) {
    unsigned long long e = (unsigned long long)blockIdx.x * 256 + threadIdx.x;
    unsigned long long start = 0;
    #pragma unroll
    for (int s = 0; s < 3; s++) {
        if (e < a.end4[s]) {
            unsigned long long base = (e - start) * 4;
            int N = a.N[s];
            int k = (int)(base / N), n = (int)(base % N);
            float4 v = *reinterpret_cast<const float4*>(a.W[s] + base);
            if (a.fmt[s]) {
                writeB1h(a.img[s], a.nkB[s], k, n,
                         __float2half_rn(v.x), __float2half_rn(v.y));
                writeB1h(a.img[s], a.nkB[s], k, n + 2,
                         __float2half_rn(v.z), __float2half_rn(v.w));
            } else {
                bf16 h0,l0,h1,l1,h2,l2,h3,l3;
                split2(v.x,h0,l0); split2(v.y,h1,l1);
                split2(v.z,h2,l2); split2(v.w,h3,l3);
                writeB2(a.img[s], a.nkB[s], k, n,     h0, h1, l0, l1);
                writeB2(a.img[s], a.nkB[s], k, n + 2, h2, h3, l2, l3);
            }
            return;
        }
        start = a.end4[s];
    }
}

// ---------------- common epilogue addend ------------------------------------
__device__ __forceinline__ float addval(const float* AddW, const float* Addb,
                                        int r, int c, int N) {
    if (AddW && r < ADDROWS) return AddW[(size_t)r * N + c];
    if (Addb && r == ADDROWS) return Addb[c];
    return 0.0f;
}

// ---------------- 64-tile bf16 3-MMA GEMM (micro chain; dual-format out) ----
__global__ __launch_bounds__(256, 2)
void gemm_bulk64(const char* __restrict__ Aimg, const char* __restrict__ Bimg,
                 int nk, int nkB, int N,
                 char* __restrict__ outBbf, int KCbf,
                 char* __restrict__ outBh,  int KCh) {
    extern __shared__ char smem_raw[];
    const uint32_t sb = smem_u32(smem_raw);
    const uint32_t stages = sb + 128;

    const int tid  = threadIdx.x;
    const int wid  = tid >> 5;
    const int lane = tid & 31;
    const int warp_m = (wid & 1) * 32;
    const int warp_n = (wid >> 1) * 32;
    const int block_row = blockIdx.y * 64;
    const int block_col = blockIdx.x * 128;

    const char* Abase = Aimg + (size_t)blockIdx.y * ((size_t)nk  * ACH64);
    const char* Bbase = Bimg + (size_t)blockIdx.x * ((size_t)nkB * BCH);

    if (tid == 0) {
        #pragma unroll
        for (int s = 0; s < NSTAGE; s++) {
            mbar_init(sb + s * 8, 1);
            mbar_init(sb + 64 + s * 8, 8);
        }
    }
    __syncthreads();

    if (tid == 0) {
        #pragma unroll
        for (int s = 0; s < NSTAGE; s++) {
            if (s < nk) {
                uint32_t mb = sb + s * 8;
                mbar_expect_tx(mb, STAGE_SZ64);
                bulk_g2s(stages + s * STAGE_SZ64,         Abase + (size_t)s * ACH64, ACH64, mb);
                bulk_g2s(stages + s * STAGE_SZ64 + ACH64, Bbase + (size_t)s * BCH,   BCH,   mb);
            }
        }
    }

    float acc[32];
    #pragma unroll
    for (int i = 0; i < 32; i++) acc[i] = 0.0f;

    const int lr = lane & 15;
    const int lc = (lane >> 4) << 3;

    int stage = 0;
    uint32_t par = 0;
    for (int it = 0; it < nk; ++it) {
        mbar_wait(sb + stage * 8, par);

        const uint32_t sA = stages + stage * STAGE_SZ64;
        const uint32_t sB = sA + ACH64;

        #pragma unroll
        for (int k2 = 0; k2 < 2; k2++) {
            uint32_t bh[8], bl[8];
            #pragma unroll
            for (int nb = 0; nb < 2; nb++) {
                uint32_t addr = sB + (k2 * 16 + lr) * B_STRIDE
                              + (warp_n + nb * 16 + lc) * 2;
                ldsm4t(&bh[nb * 4], addr);
                ldsm4t(&bl[nb * 4], addr + BHALF);
            }
            #pragma unroll
            for (int mi = 0; mi < 2; mi++) {
                uint32_t ah[4], al[4];
                uint32_t addr = sA + (warp_m + mi * 16 + lr) * A_STRIDE
                              + (k2 * 16 + lc) * 2;
                ldsm4(ah, addr);
                ldsm4(al, addr + AHALF64);
                #pragma unroll
                for (int ni = 0; ni < 4; ni++) {
                    float* d = acc + (mi * 4 + ni) * 4;
                    mma16816(d, ah, &bh[ni * 2]);
                    mma16816(d, ah, &bl[ni * 2]);
                    mma16816(d, al, &bh[ni * 2]);
                }
            }
        }

        if (lane == 0) mbar_arrive(sb + 64 + stage * 8);

        if (tid == 0 && it + NSTAGE < nk) {
            mbar_wait(sb + 64 + stage * 8, par);
            uint32_t mb = sb + stage * 8;
            mbar_expect_tx(mb, STAGE_SZ64);
            bulk_g2s(stages + stage * STAGE_SZ64,
                     Abase + (size_t)(it + NSTAGE) * ACH64, ACH64, mb);
            bulk_g2s(stages + stage * STAGE_SZ64 + ACH64,
                     Bbase + (size_t)(it + NSTAGE) * BCH, BCH, mb);
        }

        if (++stage == NSTAGE) { stage = 0; par ^= 1; }
    }

    #pragma unroll
    for (int mi = 0; mi < 2; mi++) {
        #pragma unroll
        for (int ni = 0; ni < 4; ni++) {
            const float* d = acc + (mi * 4 + ni) * 4;
            int r0 = block_row + warp_m + mi * 16 + (lane >> 2);
            int c0 = block_col + warp_n + ni * 8 + (lane & 3) * 2;
            if (outBbf) {
                bf16 h0,l0,h1,l1,h2,l2,h3,l3;
                split2(d[0],h0,l0); split2(d[1],h1,l1);
                split2(d[2],h2,l2); split2(d[3],h3,l3);
                writeB2(outBbf, KCbf, r0,     c0, h0, h1, l0, l1);
                writeB2(outBbf, KCbf, r0 + 8, c0, h2, h3, l2, l3);
            }
            if (outBh) {
                writeB1h(outBh, KCh, r0,     c0,
                         __float2half_rn(d[0]), __float2half_rn(d[1]));
                writeB1h(outBh, KCh, r0 + 8, c0,
                         __float2half_rn(d[2]), __float2half_rn(d[3]));
            }
        }
    }
}

// ---------------- 64-tile fp16 1-MMA GEMM (E4) -------------------------------
__global__ __launch_bounds__(256, 2)
void gemm_e4_f16(const char* __restrict__ Aimg, const char* __restrict__ Bimg,
                 int nk, int nkB, int N,
                 const float* __restrict__ AddW, const float* __restrict__ Addb,
                 char* __restrict__ outBh, int KCh) {
    extern __shared__ char smem_raw[];
    const uint32_t sb = smem_u32(smem_raw);
    const uint32_t stages = sb + 128;

    const int tid  = threadIdx.x;
    const int wid  = tid >> 5;
    const int lane = tid & 31;
    const int warp_m = (wid & 1) * 32;
    const int warp_n = (wid >> 1) * 32;
    const int block_row = blockIdx.y * 64;
    const int block_col = blockIdx.x * 128;

    const char* Abase = Aimg + (size_t)blockIdx.y * ((size_t)nk  * ACH64H);
    const char* Bbase = Bimg + (size_t)blockIdx.x * ((size_t)nkB * BCHH);

    if (tid == 0) {
        #pragma unroll
        for (int s = 0; s < NSTAGE; s++) {
            mbar_init(sb + s * 8, 1);
            mbar_init(sb + 64 + s * 8, 8);
        }
    }
    __syncthreads();

    if (tid == 0) {
        #pragma unroll
        for (int s = 0; s < NSTAGE; s++) {
            if (s < nk) {
                uint32_t mb = sb + s * 8;
                mbar_expect_tx(mb, STAGE_SZE4);
                bulk_g2s(stages + s * STAGE_SZE4,          Abase + (size_t)s * ACH64H, ACH64H, mb);
                bulk_g2s(stages + s * STAGE_SZE4 + ACH64H, Bbase + (size_t)s * BCHH,   BCHH,   mb);
            }
        }
    }

    float acc[32];
    #pragma unroll
    for (int i = 0; i < 32; i++) acc[i] = 0.0f;

    const int lr = lane & 15;
    const int lc = (lane >> 4) << 3;

    int stage = 0;
    uint32_t par = 0;
    for (int it = 0; it < nk; ++it) {
        mbar_wait(sb + stage * 8, par);

        const uint32_t sA = stages + stage * STAGE_SZE4;
        const uint32_t sB = sA + ACH64H;

        #pragma unroll
        for (int k2 = 0; k2 < 2; k2++) {
            uint32_t bh[8];
            #pragma unroll
            for (int nb = 0; nb < 2; nb++) {
                uint32_t addr = sB + (k2 * 16 + lr) * B_STRIDE
                              + (warp_n + nb * 16 + lc) * 2;
                ldsm4t(&bh[nb * 4], addr);
            }
            #pragma unroll
            for (int mi = 0; mi < 2; mi++) {
                uint32_t ah[4];
                uint32_t addr = sA + (warp_m + mi * 16 + lr) * A_STRIDE
                              + (k2 * 16 + lc) * 2;
                ldsm4(ah, addr);
                #pragma unroll
                for (int ni = 0; ni < 4; ni++)
                    mma16816h(acc + (mi * 4 + ni) * 4, ah, &bh[ni * 2]);
            }
        }

        if (lane == 0) mbar_arrive(sb + 64 + stage * 8);

        if (tid == 0 && it + NSTAGE < nk) {
            mbar_wait(sb + 64 + stage * 8, par);
            uint32_t mb = sb + stage * 8;
            mbar_expect_tx(mb, STAGE_SZE4);
            bulk_g2s(stages + stage * STAGE_SZE4,
                     Abase + (size_t)(it + NSTAGE) * ACH64H, ACH64H, mb);
            bulk_g2s(stages + stage * STAGE_SZE4 + ACH64H,
                     Bbase + (size_t)(it + NSTAGE) * BCHH, BCHH, mb);
        }

        if (++stage == NSTAGE) { stage = 0; par ^= 1; }
    }

    #pragma unroll
    for (int mi = 0; mi < 2; mi++) {
        #pragma unroll
        for (int ni = 0; ni < 4; ni++) {
            const float* d = acc + (mi * 4 + ni) * 4;
            int r0 = block_row + warp_m + mi * 16 + (lane >> 2);
            int c0 = block_col + warp_n + ni * 8 + (lane & 3) * 2;
            float v00 = d[0] + addval(AddW, Addb, r0,     c0,     N);
            float v01 = d[1] + addval(AddW, Addb, r0,     c0 + 1, N);
            float v10 = d[2] + addval(AddW, Addb, r0 + 8, c0,     N);
            float v11 = d[3] + addval(AddW, Addb, r0 + 8, c0 + 1, N);
            writeB1h(outBh, KCh, r0,     c0, __float2half_rn(v00), __float2half_rn(v01));
            writeB1h(outBh, KCh, r0 + 8, c0, __float2half_rn(v10), __float2half_rn(v11));
        }
    }
}

// ---------------- 128-tile fp16 1-MMA GEMM (G and out) -----------------------
__global__ __launch_bounds__(256, 2)
void gemm_f16(const char* __restrict__ Aimg, const char* __restrict__ Bimg,
              int nk, int nkB, int N,
              const float* __restrict__ BiasN,
              float* __restrict__ Cf,
              char* __restrict__ outAh, int KCo) {
    extern __shared__ char smem_raw[];
    const uint32_t sb = smem_u32(smem_raw);
    const uint32_t stages = sb + 128;

    const int tid  = threadIdx.x;
    const int wid  = tid >> 5;
    const int lane = tid & 31;
    const int warp_m = (wid & 1) * 64;
    const int warp_n = (wid >> 1) * 32;
    const int block_row = blockIdx.y * 128;
    const int block_col = blockIdx.x * 128;

    const char* Abase = Aimg + (size_t)blockIdx.y * ((size_t)nk  * ACHH);
    const char* Bbase = Bimg + (size_t)blockIdx.x * ((size_t)nkB * BCHH);

    if (tid == 0) {
        #pragma unroll
        for (int s = 0; s < NSTAGE; s++) {
            mbar_init(sb + s * 8, 1);
            mbar_init(sb + 64 + s * 8, 8);
        }
    }
    __syncthreads();

    if (tid == 0) {
        #pragma unroll
        for (int s = 0; s < NSTAGE; s++) {
            if (s < nk) {
                uint32_t mb = sb + s * 8;
                mbar_expect_tx(mb, STAGE_SZH);
                bulk_g2s(stages + s * STAGE_SZH,        Abase + (size_t)s * ACHH, ACHH, mb);
                bulk_g2s(stages + s * STAGE_SZH + ACHH, Bbase + (size_t)s * BCHH, BCHH, mb);
            }
        }
    }

    float acc[64];
    #pragma unroll
    for (int i = 0; i < 64; i++) acc[i] = 0.0f;

    const int lr = lane & 15;
    const int lc = (lane >> 4) << 3;

    int stage = 0;
    uint32_t par = 0;
    for (int it = 0; it < nk; ++it) {
        mbar_wait(sb + stage * 8, par);

        const uint32_t sA = stages + stage * STAGE_SZH;
        const uint32_t sB = sA + ACHH;

        #pragma unroll
        for (int k2 = 0; k2 < 2; k2++) {
            uint32_t bh[8];
            #pragma unroll
            for (int nb = 0; nb < 2; nb++) {
                uint32_t addr = sB + (k2 * 16 + lr) * B_STRIDE
                              + (warp_n + nb * 16 + lc) * 2;
                ldsm4t(&bh[nb * 4], addr);
            }
            #pragma unroll
            for (int mi = 0; mi < 4; mi++) {
                uint32_t ah[4];
                uint32_t addr = sA + (warp_m + mi * 16 + lr) * A_STRIDE
                              + (k2 * 16 + lc) * 2;
                ldsm4(ah, addr);
                #pragma unroll
                for (int ni = 0; ni < 4; ni++)
                    mma16816h(acc + (mi * 4 + ni) * 4, ah, &bh[ni * 2]);
            }
        }

        if (lane == 0) mbar_arrive(sb + 64 + stage * 8);

        if (tid == 0 && it + NSTAGE < nk) {
            mbar_wait(sb + 64 + stage * 8, par);
            uint32_t mb = sb + stage * 8;
            mbar_expect_tx(mb, STAGE_SZH);
            bulk_g2s(stages + stage * STAGE_SZH,
                     Abase + (size_t)(it + NSTAGE) * ACHH, ACHH, mb);
            bulk_g2s(stages + stage * STAGE_SZH + ACHH,
                     Bbase + (size_t)(it + NSTAGE) * BCHH, BCHH, mb);
        }

        if (++stage == NSTAGE) { stage = 0; par ^= 1; }
    }

    #pragma unroll
    for (int mi = 0; mi < 4; mi++) {
        #pragma unroll
        for (int ni = 0; ni < 4; ni++) {
            const float* d = acc + (mi * 4 + ni) * 4;
            int r0 = block_row + warp_m + mi * 16 + (lane >> 2);
            int c0 = block_col + warp_n + ni * 8 + (lane & 3) * 2;
            if (Cf) {
                float b0 = BiasN ? BiasN[c0]     : 0.0f;
                float b1 = BiasN ? BiasN[c0 + 1] : 0.0f;
                *reinterpret_cast<float2*>(Cf + (size_t)r0 * N + c0) =
                    make_float2(d[0] + b0, d[1] + b1);
                *reinterpret_cast<float2*>(Cf + (size_t)(r0 + 8) * N + c0) =
                    make_float2(d[2] + b0, d[3] + b1);
            } else {
                writeAh(outAh, KCo, r0,     c0,
                        __float2half_rn(d[0]), __float2half_rn(d[1]));
                writeAh(outAh, KCo, r0 + 8, c0,
                        __float2half_rn(d[2]), __float2half_rn(d[3]));
            }
        }
    }
}

// ---------------- host ------------------------------------------------------
template <typename T>
static T* sym_addr(const void* symbol) {
    void* p = nullptr;
    cudaGetSymbolAddress(&p, symbol);
    return reinterpret_cast<T*>(p);
}

extern "C" void kernel_launch(void* const* d_in, const int* in_sizes, int n_in,
                              void* d_out, int out_size) {
    const float* state  = (const float*)d_in[0];
    const float* action = (const float*)d_in[1];
    const float* task   = (const float*)d_in[2];
    // d_in[3..18]: dead cx branch weights
    const float* W_l1 = (const float*)d_in[19];
    const float* b_l1 = (const float*)d_in[20];
    const float* W_l2 = (const float*)d_in[21];
    const float* b_l2 = (const float*)d_in[22];
    const float* W_l3 = (const float*)d_in[23];
    const float* b_l3 = (const float*)d_in[24];
    const float* W_l4 = (const float*)d_in[25];
    const float* b_l4 = (const float*)d_in[26];
    const float* W_l5 = (const float*)d_in[27];
    const float* b_l5 = (const float*)d_in[28];
    float* out = (float*)d_out;

    cudaFuncSetAttribute(gemm_bulk64,
                         cudaFuncAttributeMaxDynamicSharedMemorySize, SMEM_TOT64);
    cudaFuncSetAttribute(gemm_e4_f16,
                         cudaFuncAttributeMaxDynamicSharedMemorySize, SMEM_TOTE4);
    cudaFuncSetAttribute(gemm_f16,
                         cudaFuncAttributeMaxDynamicSharedMemorySize, SMEM_TOTH);

    char* ctxH   = sym_addr<char>(g_ctxH);
    char* catA   = sym_addr<char>(g_catA);
    char* w2aA   = sym_addr<char>(g_W2aA);
    char* w3aA   = sym_addr<char>(g_W3aA);
    char* w4aBbf = sym_addr<char>(g_W4aBbf);
    char* c34Bbf = sym_addr<char>(g_C34Bbf);
    char* stackB = sym_addr<char>(g_stackB);
    char* e4B    = sym_addr<char>(g_E4B);
    char* gA     = sym_addr<char>(g_GA);
    char* w5B    = sym_addr<char>(g_W5B);

    // 0: ctx' fp16 A-image
    build_ctx<<<BATCH, 256>>>(state, task, action);
    // 1: concat fp16 A-image [E1|A2|A3]
    split_cat<<<5248, 512>>>(W_l1, b_l1, W_l2, b_l2, W_l3, b_l3);
    // 2,3: bf16-split A-images of W2a, W3a (micro chain full accuracy)
    split_a64<<<2048, 256>>>(W_l2, w2aA, 32);
    split_a64<<<1024, 256>>>(W_l3, w3aA, 32);
    // 4: B-images: W4a (bf16 split + fp16 single copies), W5 (fp16 single)
    {
        SplitArgs sa;
        sa.W[0] = W_l4; sa.img[0] = w4aBbf;                     sa.N[0] = 512;  sa.nkB[0] = 32;  sa.fmt[0] = 0;
        sa.end4[0] = 1024ull * 512 / 4;
        sa.W[1] = W_l4; sa.img[1] = stackB + (size_t)96 * BCHH; sa.N[1] = 512;  sa.nkB[1] = 128; sa.fmt[1] = 1;
        sa.end4[1] = sa.end4[0] + 1024ull * 512 / 4;
        sa.W[2] = W_l5; sa.img[2] = w5B;                        sa.N[2] = 1024; sa.nkB[2] = 16;  sa.fmt[2] = 1;
        sa.end4[2] = sa.end4[1] + 512ull * 1024 / 4;
        split_all<<<(unsigned)((sa.end4[2] + 255) / 256), 256>>>(sa);
    }

    // 5: C34 = W3a@W4a -> bf16 c34Bbf AND fp16 stack chunks 64..95
    gemm_bulk64<<<dim3(4, 16), 256, SMEM_TOT64>>>(
        w3aA, w4aBbf, 32, 32, 512,
        c34Bbf, 32, stackB + (size_t)64 * BCHH, 128);
    // 6: C234 = W2a@C34 -> fp16 stack chunks 0..63
    gemm_bulk64<<<dim3(4, 32), 256, SMEM_TOT64>>>(
        w2aA, c34Bbf, 32, 32, 512,
        nullptr, 0, stackB, 128);
    // 7: E4 = [E1|A2|A3]@[C234;C34;W4a] + aug(W4b,b4) -> fp16 single B-image
    gemm_e4_f16<<<dim3(4, 82), 256, SMEM_TOTE4>>>(
        catA, stackB, 128, 128, 512,
        W_l4 + (size_t)1024 * 512, b_l4, e4B, 164);
    // 8: G = ctx'@E4 (fp16 1-MMA) -> fp16 single A-image
    gemm_f16<<<dim3(4, BATCH / 128), 256, SMEM_TOTH>>>(
        ctxH, e4B, 161, 164, 512, nullptr, nullptr, gA, 16);
    // 9: out = G@W5 + b5 (fp16 1-MMA)
    gemm_f16<<<dim3(8, BATCH / 128), 256, SMEM_TOTH>>>(
        gA, w5B, 16, 16, 1024, b_l5, out, nullptr, 0);
}